// round 1
// baseline (speedup 1.0000x reference)
#include <cuda_runtime.h>
#include <cstddef>

// Problem dims
#define BB 2048
#define TT 64
#define II 128
#define HH 1024
#define GG 4096  // 4*H

// Static device scratch (no allocations allowed)
__device__ float g_h1[BB * HH];
__device__ float g_c1[BB * HH];
__device__ float g_h2[BB * HH];
__device__ float g_c2[BB * HH];
__device__ float g_gates[(size_t)BB * GG];

// ---------------------------------------------------------------------------
// Tiled SGEMM computing  C[M,N] = A1[M,K1] @ W1[N,K1]^T + A2[M,K2] @ W2[N,K2]^T
//                               + bias1[N] (+ bias2[N])
// BM=BN=128, BK=16, 256 threads, 8x8 per-thread micro tile.
// M = 2048 fixed via grid; N via grid.x*128. All dims multiples of tile sizes.
// ---------------------------------------------------------------------------
__global__ __launch_bounds__(256, 2)
void sgemm_dual(const float* __restrict__ A1, int lda1, int K1,
                const float* __restrict__ A2, int lda2, int K2,
                const float* __restrict__ W1,   // [N, K1] row-major
                const float* __restrict__ W2,   // [N, K2] row-major
                const float* __restrict__ bias1,
                const float* __restrict__ bias2,
                float* __restrict__ C, int ldc)
{
    __shared__ float As[16][132];   // [k][m], padded to kill store conflicts
    __shared__ float Ws[16][132];   // [k][n]

    const int tid = threadIdx.x;
    const int bm = blockIdx.y * 128;
    const int bn = blockIdx.x * 128;
    const int tx = tid & 15;        // micro-tile col group
    const int ty = tid >> 4;        // micro-tile row group

    float acc[8][8];
#pragma unroll
    for (int i = 0; i < 8; i++)
#pragma unroll
        for (int j = 0; j < 8; j++) acc[i][j] = 0.f;

    auto run = [&](const float* __restrict__ A, int lda,
                   const float* __restrict__ W, int ldw, int K) {
        for (int k0 = 0; k0 < K; k0 += 16) {
            // Load 128x16 A tile and 128x16 W tile (float4 along K), store transposed.
#pragma unroll
            for (int l = 0; l < 2; l++) {
                int f   = tid + l * 256;       // 512 float4 per tile
                int row = f >> 2;
                int kc  = (f & 3) * 4;
                float4 va = *reinterpret_cast<const float4*>(
                    A + (size_t)(bm + row) * lda + k0 + kc);
                As[kc + 0][row] = va.x;
                As[kc + 1][row] = va.y;
                As[kc + 2][row] = va.z;
                As[kc + 3][row] = va.w;
                float4 vw = *reinterpret_cast<const float4*>(
                    W + (size_t)(bn + row) * ldw + k0 + kc);
                Ws[kc + 0][row] = vw.x;
                Ws[kc + 1][row] = vw.y;
                Ws[kc + 2][row] = vw.z;
                Ws[kc + 3][row] = vw.w;
            }
            __syncthreads();
#pragma unroll
            for (int k = 0; k < 16; k++) {
                float a[8], b[8];
                *reinterpret_cast<float4*>(a)     = *reinterpret_cast<float4*>(&As[k][ty * 8]);
                *reinterpret_cast<float4*>(a + 4) = *reinterpret_cast<float4*>(&As[k][ty * 8 + 4]);
                *reinterpret_cast<float4*>(b)     = *reinterpret_cast<float4*>(&Ws[k][tx * 8]);
                *reinterpret_cast<float4*>(b + 4) = *reinterpret_cast<float4*>(&Ws[k][tx * 8 + 4]);
#pragma unroll
                for (int i = 0; i < 8; i++)
#pragma unroll
                    for (int j = 0; j < 8; j++)
                        acc[i][j] = fmaf(a[i], b[j], acc[i][j]);
            }
            __syncthreads();
        }
    };

    run(A1, lda1, W1, K1, K1);
    if (K2 > 0) run(A2, lda2, W2, K2, K2);

    // Epilogue: bias add + store (vectorized)
#pragma unroll
    for (int i = 0; i < 8; i++) {
        int row = bm + ty * 8 + i;
#pragma unroll
        for (int j = 0; j < 8; j += 4) {
            int col = bn + tx * 8 + j;
            float4 v;
            v.x = acc[i][j + 0];
            v.y = acc[i][j + 1];
            v.z = acc[i][j + 2];
            v.w = acc[i][j + 3];
            if (bias1) {
                float4 b1 = *reinterpret_cast<const float4*>(bias1 + col);
                v.x += b1.x; v.y += b1.y; v.z += b1.z; v.w += b1.w;
            }
            if (bias2) {
                float4 b2 = *reinterpret_cast<const float4*>(bias2 + col);
                v.x += b2.x; v.y += b2.y; v.z += b2.z; v.w += b2.w;
            }
            *reinterpret_cast<float4*>(C + (size_t)row * ldc + col) = v;
        }
    }
}

// ---------------------------------------------------------------------------
// LSTM cell pointwise: gates [B,4H] (order i,f,g,o), updates h,c in place.
// ---------------------------------------------------------------------------
__device__ __forceinline__ float sigmoidf_(float x) {
    return 1.f / (1.f + expf(-x));
}

__global__ void lstm_cell(const float* __restrict__ gates,
                          float* __restrict__ h, float* __restrict__ c)
{
    int idx = blockIdx.x * blockDim.x + threadIdx.x;  // over B*H
    int b = idx >> 10;
    int j = idx & 1023;
    const float* g = gates + (size_t)b * GG;
    float ig = sigmoidf_(g[j]);
    float fg = sigmoidf_(g[j + HH]);
    float gg = tanhf(g[j + 2 * HH]);
    float og = sigmoidf_(g[j + 3 * HH]);
    float cn = fg * c[idx] + ig * gg;
    c[idx] = cn;
    h[idx] = og * tanhf(cn);
}

// ---------------------------------------------------------------------------
extern "C" void kernel_launch(void* const* d_in, const int* in_sizes, int n_in,
                              void* d_out, int out_size)
{
    const float* x     = (const float*)d_in[0];   // [B,T,I]
    const float* h1_in = (const float*)d_in[1];
    const float* c1_in = (const float*)d_in[2];
    const float* h2_in = (const float*)d_in[3];
    const float* c2_in = (const float*)d_in[4];
    const float* w_ih1 = (const float*)d_in[5];   // [4H, I]
    const float* w_hh1 = (const float*)d_in[6];   // [4H, H]
    const float* b_ih1 = (const float*)d_in[7];
    const float* b_hh1 = (const float*)d_in[8];
    const float* w_ih2 = (const float*)d_in[9];   // [4H, H]
    const float* w_hh2 = (const float*)d_in[10];  // [4H, H]
    const float* b_ih2 = (const float*)d_in[11];
    const float* b_hh2 = (const float*)d_in[12];
    const float* fc_w  = (const float*)d_in[13];  // [I, H]
    const float* fc_b  = (const float*)d_in[14];

    float* out = (float*)d_out;  // [B*T*I] output_seq, then h1,c1,h2,c2

    float *h1p, *c1p, *h2p, *c2p, *gatesp;
    cudaGetSymbolAddress((void**)&h1p, g_h1);
    cudaGetSymbolAddress((void**)&c1p, g_c1);
    cudaGetSymbolAddress((void**)&h2p, g_h2);
    cudaGetSymbolAddress((void**)&c2p, g_c2);
    cudaGetSymbolAddress((void**)&gatesp, g_gates);

    const size_t stateBytes = (size_t)BB * HH * sizeof(float);
    cudaMemcpyAsync(h1p, h1_in, stateBytes, cudaMemcpyDeviceToDevice);
    cudaMemcpyAsync(c1p, c1_in, stateBytes, cudaMemcpyDeviceToDevice);
    cudaMemcpyAsync(h2p, h2_in, stateBytes, cudaMemcpyDeviceToDevice);
    cudaMemcpyAsync(c2p, c2_in, stateBytes, cudaMemcpyDeviceToDevice);

    dim3 blk(256);
    dim3 grdGates(GG / 128, BB / 128);  // (32,16)
    dim3 grdFc(II / 128, BB / 128);     // (1,16)
    int cellBlocks = (BB * HH) / 256;

    for (int t = 0; t < TT; t++) {
        // layer1 gates = x_t @ w_ih1^T + h1 @ w_hh1^T + b_ih1 + b_hh1
        sgemm_dual<<<grdGates, blk>>>(x + (size_t)t * II, TT * II, II,
                                      h1p, HH, HH,
                                      w_ih1, w_hh1, b_ih1, b_hh1,
                                      gatesp, GG);
        lstm_cell<<<cellBlocks, 256>>>(gatesp, h1p, c1p);

        // layer2 gates = h1 @ w_ih2^T + h2 @ w_hh2^T + b_ih2 + b_hh2
        sgemm_dual<<<grdGates, blk>>>(h1p, HH, HH,
                                      h2p, HH, HH,
                                      w_ih2, w_hh2, b_ih2, b_hh2,
                                      gatesp, GG);
        lstm_cell<<<cellBlocks, 256>>>(gatesp, h2p, c2p);

        // y_t = h2 @ fc_w^T + fc_b  -> out[:, t, :]
        sgemm_dual<<<grdFc, blk>>>(h2p, HH, HH,
                                   nullptr, 0, 0,
                                   fc_w, nullptr, fc_b, nullptr,
                                   out + (size_t)t * II, TT * II);
    }

    // Final states appended after output_seq: h1, c1, h2, c2
    float* tail = out + (size_t)BB * TT * II;
    cudaMemcpyAsync(tail + 0 * (size_t)BB * HH, h1p, stateBytes, cudaMemcpyDeviceToDevice);
    cudaMemcpyAsync(tail + 1 * (size_t)BB * HH, c1p, stateBytes, cudaMemcpyDeviceToDevice);
    cudaMemcpyAsync(tail + 2 * (size_t)BB * HH, h2p, stateBytes, cudaMemcpyDeviceToDevice);
    cudaMemcpyAsync(tail + 3 * (size_t)BB * HH, c2p, stateBytes, cudaMemcpyDeviceToDevice);
}

// round 3
// speedup vs baseline: 3.3116x; 3.3116x over previous
#include <cuda_runtime.h>
#include <cstdint>
#include <cstddef>

#define BB 2048
#define TT 64
#define II 128
#define HH 1024

// Static device scratch (no allocations allowed)
__device__ float g_h1[2][(size_t)BB * HH];
__device__ float g_c1[(size_t)BB * HH];
__device__ float g_c2[(size_t)BB * HH];
__device__ float g_hist[(size_t)(TT + 1) * BB * HH];  // h2 history: slot 0 = initial

__device__ __forceinline__ uint32_t f2tf(float x) {
    uint32_t u;
    asm("cvt.rna.tf32.f32 %0, %1;" : "=r"(u) : "f"(x));
    return u;
}
__device__ __forceinline__ float sigf(float x) { return 1.f / (1.f + expf(-x)); }

__device__ __forceinline__ void mma8(float* c, uint32_t a0, uint32_t a1, uint32_t a2, uint32_t a3,
                                     uint32_t b0, uint32_t b1) {
    asm volatile(
        "mma.sync.aligned.m16n8k8.row.col.f32.tf32.tf32.f32 "
        "{%0,%1,%2,%3},{%4,%5,%6,%7},{%8,%9},{%0,%1,%2,%3};"
        : "+f"(c[0]), "+f"(c[1]), "+f"(c[2]), "+f"(c[3])
        : "r"(a0), "r"(a1), "r"(a2), "r"(a3), "r"(b0), "r"(b1));
}

// ---------------------------------------------------------------------------
// Gate GEMM + fused LSTM cell.
//  gates[128 x 256-tile] = A1[.,K1] @ W1^T + A2[.,HH] @ W2^T   (K staged 32)
//  N-tile is gate-permuted: cols [g*64 + u] = gate g of units tile_n*64+u.
//  Epilogue: smem transpose stage -> per-thread i,f,g,o -> h,c update.
// ---------------------------------------------------------------------------
__global__ __launch_bounds__(256, 1)
void gate_gemm(const float* __restrict__ A1, int lda1, int K1,
               const float* __restrict__ A2,
               const float* __restrict__ W1, int ldw1,
               const float* __restrict__ W2,
               const float* __restrict__ b1, const float* __restrict__ b2,
               float* __restrict__ Hout, float* __restrict__ Cst)
{
    extern __shared__ __align__(16) char smem[];
    constexpr int OFF_A = 1024;
    constexpr int ASZ = 128 * 36 * 4;
    constexpr int OFF_B = OFF_A + 2 * ASZ;
    constexpr int BSZ = 256 * 36 * 4;

    float* bias = (float*)smem;
    const int tid = threadIdx.x, lane = tid & 31, wid = tid >> 5;
    const int gid = lane >> 2, tig = lane & 3;
    const int bm = blockIdx.y * 128, tile_n = blockIdx.x;
    const int mwarp = (wid >> 2) * 64, nwarp = (wid & 3) * 64;

    {   // summed bias, permuted (256 threads, 256 cols)
        int wr = (tid >> 6) * HH + tile_n * 64 + (tid & 63);
        bias[tid] = b1[wr] + b2[wr];
    }

    float acc[4][8][4];
#pragma unroll
    for (int a = 0; a < 4; a++)
#pragma unroll
        for (int b = 0; b < 8; b++)
#pragma unroll
            for (int c = 0; c < 4; c++) acc[a][b][c] = 0.f;

    const int stages = (K1 + HH) / 32;
    float4 pa[4], pb[8];

    auto ldg = [&](int s) {
        int k0 = s * 32;
        const float* A; const float* W; int lda, ldw, kk;
        if (k0 < K1) { A = A1; W = W1; lda = lda1; ldw = ldw1; kk = k0; }
        else         { A = A2; W = W2; lda = HH;  ldw = HH;  kk = k0 - K1; }
#pragma unroll
        for (int i = 0; i < 4; i++) {
            int f = tid + i * 256, row = f >> 3, kc = f & 7;
            pa[i] = *(const float4*)(A + (size_t)(bm + row) * lda + kk + kc * 4);
        }
#pragma unroll
        for (int i = 0; i < 8; i++) {
            int f = tid + i * 256, row = f >> 3, kc = f & 7;
            int wr = (row >> 6) * HH + tile_n * 64 + (row & 63);
            pb[i] = *(const float4*)(W + (size_t)wr * ldw + kk + kc * 4);
        }
    };
    auto sts = [&](int buf) {
        uint32_t* As = (uint32_t*)(smem + OFF_A + buf * ASZ);
        uint32_t* Bs = (uint32_t*)(smem + OFF_B + buf * BSZ);
#pragma unroll
        for (int i = 0; i < 4; i++) {
            int f = tid + i * 256, row = f >> 3, kc = f & 7;
            uint4 v = {f2tf(pa[i].x), f2tf(pa[i].y), f2tf(pa[i].z), f2tf(pa[i].w)};
            *(uint4*)(As + row * 36 + kc * 4) = v;
        }
#pragma unroll
        for (int i = 0; i < 8; i++) {
            int f = tid + i * 256, row = f >> 3, kc = f & 7;
            uint4 v = {f2tf(pb[i].x), f2tf(pb[i].y), f2tf(pb[i].z), f2tf(pb[i].w)};
            *(uint4*)(Bs + row * 36 + kc * 4) = v;
        }
    };
    auto domma = [&](int buf) {
        const uint32_t* As = (const uint32_t*)(smem + OFF_A + buf * ASZ);
        const uint32_t* Bs = (const uint32_t*)(smem + OFF_B + buf * BSZ);
#pragma unroll
        for (int ks = 0; ks < 4; ks++) {
            int kk = ks * 8 + tig;
            uint32_t bf[8][2];
#pragma unroll
            for (int n = 0; n < 8; n++) {
                int col = nwarp + n * 8 + gid;
                bf[n][0] = Bs[col * 36 + kk];
                bf[n][1] = Bs[col * 36 + kk + 4];
            }
#pragma unroll
            for (int mi = 0; mi < 4; mi++) {
                int row = mwarp + mi * 16 + gid;
                uint32_t a0 = As[row * 36 + kk];
                uint32_t a1 = As[(row + 8) * 36 + kk];
                uint32_t a2 = As[row * 36 + kk + 4];
                uint32_t a3 = As[(row + 8) * 36 + kk + 4];
#pragma unroll
                for (int n = 0; n < 8; n++)
                    mma8(acc[mi][n], a0, a1, a2, a3, bf[n][0], bf[n][1]);
            }
        }
    };

    ldg(0); sts(0); __syncthreads();
    for (int s = 0; s < stages; s++) {
        int buf = s & 1;
        if (s + 1 < stages) ldg(s + 1);
        domma(buf);
        if (s + 1 < stages) sts(buf ^ 1);
        __syncthreads();
    }

    // Epilogue: two 64-row phases staged through smem (reuses A/B buffers)
    float* stage = (float*)(smem + 1024);
#pragma unroll
    for (int p = 0; p < 2; p++) {
        if ((wid >> 2) == p) {
#pragma unroll
            for (int mi = 0; mi < 4; mi++)
#pragma unroll
                for (int n = 0; n < 8; n++) {
                    int r0 = mi * 16 + gid, c = nwarp + n * 8 + 2 * tig;
                    stage[r0 * 260 + c]           = acc[mi][n][0];
                    stage[r0 * 260 + c + 1]       = acc[mi][n][1];
                    stage[(r0 + 8) * 260 + c]     = acc[mi][n][2];
                    stage[(r0 + 8) * 260 + c + 1] = acc[mi][n][3];
                }
        }
        __syncthreads();
        {
            int r = tid >> 2, u0 = (tid & 3) * 16;
            int m = bm + p * 64 + r;
            float* crow = Cst + (size_t)m * HH + tile_n * 64;
            float* hrow = Hout + (size_t)m * HH + tile_n * 64;
#pragma unroll
            for (int jb = 0; jb < 4; jb++) {
                float4 cv = *(float4*)(crow + u0 + jb * 4);
                float4 hv;
                float* cvp = (float*)&cv;
                float* hvp = (float*)&hv;
#pragma unroll
                for (int e = 0; e < 4; e++) {
                    int u = u0 + jb * 4 + e;
                    float iv = sigf(stage[r * 260 + u] + bias[u]);
                    float fv = sigf(stage[r * 260 + 64 + u] + bias[64 + u]);
                    float gv = tanhf(stage[r * 260 + 128 + u] + bias[128 + u]);
                    float ov = sigf(stage[r * 260 + 192 + u] + bias[192 + u]);
                    float cn = fv * cvp[e] + iv * gv;
                    cvp[e] = cn;
                    hvp[e] = ov * tanhf(cn);
                }
                *(float4*)(crow + u0 + jb * 4) = cv;
                *(float4*)(hrow + u0 + jb * 4) = hv;
            }
        }
        __syncthreads();
    }
}

// ---------------------------------------------------------------------------
// Batched fc over the whole h2 history: OUT[(b*T+t), :] = hist[t+1][b] @ W^T + bias
// A rows are linear r = t*B + b (hist layout [t][b][h]).
// ---------------------------------------------------------------------------
__global__ __launch_bounds__(256, 1)
void fc_gemm(const float* __restrict__ A, const float* __restrict__ W,
             const float* __restrict__ bias_g, float* __restrict__ out)
{
    extern __shared__ __align__(16) char smem[];
    constexpr int OFF_A = 1024;
    constexpr int ASZ = 128 * 36 * 4;
    constexpr int OFF_B = OFF_A + 2 * ASZ;

    float* bias = (float*)smem;
    const int tid = threadIdx.x, lane = tid & 31, wid = tid >> 5;
    const int gid = lane >> 2, tig = lane & 3;
    const int bm = blockIdx.x * 128;
    const int mwarp = (wid >> 2) * 64, nwarp = (wid & 3) * 32;

    if (tid < II) bias[tid] = bias_g[tid];

    float acc[4][4][4];
#pragma unroll
    for (int a = 0; a < 4; a++)
#pragma unroll
        for (int b = 0; b < 4; b++)
#pragma unroll
            for (int c = 0; c < 4; c++) acc[a][b][c] = 0.f;

    float4 pa[4], pb[4];
    auto ldg = [&](int s) {
        int kk = s * 32;
#pragma unroll
        for (int i = 0; i < 4; i++) {
            int f = tid + i * 256, row = f >> 3, kc = f & 7;
            pa[i] = *(const float4*)(A + (size_t)(bm + row) * HH + kk + kc * 4);
            pb[i] = *(const float4*)(W + (size_t)row * HH + kk + kc * 4);
        }
    };
    auto sts = [&](int buf) {
        uint32_t* As = (uint32_t*)(smem + OFF_A + buf * ASZ);
        uint32_t* Bs = (uint32_t*)(smem + OFF_B + buf * ASZ);
#pragma unroll
        for (int i = 0; i < 4; i++) {
            int f = tid + i * 256, row = f >> 3, kc = f & 7;
            uint4 va = {f2tf(pa[i].x), f2tf(pa[i].y), f2tf(pa[i].z), f2tf(pa[i].w)};
            *(uint4*)(As + row * 36 + kc * 4) = va;
            uint4 vb = {f2tf(pb[i].x), f2tf(pb[i].y), f2tf(pb[i].z), f2tf(pb[i].w)};
            *(uint4*)(Bs + row * 36 + kc * 4) = vb;
        }
    };
    auto domma = [&](int buf) {
        const uint32_t* As = (const uint32_t*)(smem + OFF_A + buf * ASZ);
        const uint32_t* Bs = (const uint32_t*)(smem + OFF_B + buf * ASZ);
#pragma unroll
        for (int ks = 0; ks < 4; ks++) {
            int kk = ks * 8 + tig;
            uint32_t bf[4][2];
#pragma unroll
            for (int n = 0; n < 4; n++) {
                int col = nwarp + n * 8 + gid;
                bf[n][0] = Bs[col * 36 + kk];
                bf[n][1] = Bs[col * 36 + kk + 4];
            }
#pragma unroll
            for (int mi = 0; mi < 4; mi++) {
                int row = mwarp + mi * 16 + gid;
                uint32_t a0 = As[row * 36 + kk];
                uint32_t a1 = As[(row + 8) * 36 + kk];
                uint32_t a2 = As[row * 36 + kk + 4];
                uint32_t a3 = As[(row + 8) * 36 + kk + 4];
#pragma unroll
                for (int n = 0; n < 4; n++)
                    mma8(acc[mi][n], a0, a1, a2, a3, bf[n][0], bf[n][1]);
            }
        }
    };

    ldg(0); sts(0); __syncthreads();
    for (int s = 0; s < 32; s++) {
        int buf = s & 1;
        if (s + 1 < 32) ldg(s + 1);
        domma(buf);
        if (s + 1 < 32) sts(buf ^ 1);
        __syncthreads();
    }

    // Epilogue: scatter rows to out[b][t][:]
#pragma unroll
    for (int mi = 0; mi < 4; mi++) {
        int r0 = bm + mwarp + mi * 16 + gid;
#pragma unroll
        for (int half = 0; half < 2; half++) {
            int m = r0 + half * 8;
            size_t orow = ((size_t)(m & (BB - 1)) * TT + (m >> 11)) * II;
#pragma unroll
            for (int n = 0; n < 4; n++) {
                int c = nwarp + n * 8 + 2 * tig;
                float2 v;
                v.x = acc[mi][n][half * 2 + 0] + bias[c];
                v.y = acc[mi][n][half * 2 + 1] + bias[c + 1];
                *(float2*)(out + orow + c) = v;
            }
        }
    }
}

// ---------------------------------------------------------------------------
extern "C" void kernel_launch(void* const* d_in, const int* in_sizes, int n_in,
                              void* d_out, int out_size)
{
    const float* x     = (const float*)d_in[0];
    const float* h1_in = (const float*)d_in[1];
    const float* c1_in = (const float*)d_in[2];
    const float* h2_in = (const float*)d_in[3];
    const float* c2_in = (const float*)d_in[4];
    const float* w_ih1 = (const float*)d_in[5];
    const float* w_hh1 = (const float*)d_in[6];
    const float* b_ih1 = (const float*)d_in[7];
    const float* b_hh1 = (const float*)d_in[8];
    const float* w_ih2 = (const float*)d_in[9];
    const float* w_hh2 = (const float*)d_in[10];
    const float* b_ih2 = (const float*)d_in[11];
    const float* b_hh2 = (const float*)d_in[12];
    const float* fc_w  = (const float*)d_in[13];
    const float* fc_b  = (const float*)d_in[14];
    float* out = (float*)d_out;

    float *h1p, *c1p, *c2p, *histp;
    cudaGetSymbolAddress((void**)&h1p, g_h1);
    cudaGetSymbolAddress((void**)&c1p, g_c1);
    cudaGetSymbolAddress((void**)&c2p, g_c2);
    cudaGetSymbolAddress((void**)&histp, g_hist);

    const size_t SN = (size_t)BB * HH;
    const size_t SB = SN * sizeof(float);
    cudaMemcpyAsync(h1p, h1_in, SB, cudaMemcpyDeviceToDevice);
    cudaMemcpyAsync(c1p, c1_in, SB, cudaMemcpyDeviceToDevice);
    cudaMemcpyAsync(c2p, c2_in, SB, cudaMemcpyDeviceToDevice);
    cudaMemcpyAsync(histp, h2_in, SB, cudaMemcpyDeviceToDevice);  // slot 0

    constexpr int SMEM_GATE = 1024 + 2 * (128 * 36 * 4) + 2 * (256 * 36 * 4);  // 111616
    constexpr int SMEM_FC   = 1024 + 4 * (128 * 36 * 4);                       //  74752
    cudaFuncSetAttribute(gate_gemm, cudaFuncAttributeMaxDynamicSharedMemorySize, SMEM_GATE);
    cudaFuncSetAttribute(fc_gemm, cudaFuncAttributeMaxDynamicSharedMemorySize, SMEM_FC);

    dim3 blk(256);
    dim3 grdG(16, 16);

    for (int t = 0; t < TT; t++) {
        float* h1r = h1p + (size_t)(t & 1) * SN;
        float* h1w = h1p + (size_t)(1 - (t & 1)) * SN;
        float* h2r = histp + (size_t)t * SN;
        float* h2w = histp + (size_t)(t + 1) * SN;

        gate_gemm<<<grdG, blk, SMEM_GATE>>>(
            x + (size_t)t * II, TT * II, II, h1r,
            w_ih1, II, w_hh1, b_ih1, b_hh1, h1w, c1p);

        gate_gemm<<<grdG, blk, SMEM_GATE>>>(
            h1w, HH, HH, h2r,
            w_ih2, HH, w_hh2, b_ih2, b_hh2, h2w, c2p);
    }

    // Batched fc over all timesteps
    fc_gemm<<<1024, blk, SMEM_FC>>>(histp + SN, fc_w, fc_b, out);

    // Final states: output_seq ‖ h1 ‖ c1 ‖ h2 ‖ c2
    float* tail = out + (size_t)BB * TT * II;
    cudaMemcpyAsync(tail + 0 * SN, h1p, SB, cudaMemcpyDeviceToDevice);               // h1 final in buf 0
    cudaMemcpyAsync(tail + 1 * SN, c1p, SB, cudaMemcpyDeviceToDevice);
    cudaMemcpyAsync(tail + 2 * SN, histp + (size_t)TT * SN, SB, cudaMemcpyDeviceToDevice);
    cudaMemcpyAsync(tail + 3 * SN, c2p, SB, cudaMemcpyDeviceToDevice);
}

// round 4
// speedup vs baseline: 3.7197x; 1.1232x over previous
#include <cuda_runtime.h>
#include <cstdint>
#include <cstddef>

#define BB 2048
#define TT 64
#define II 128
#define HH 1024

// Static device scratch (no allocations allowed)
__device__ float g_h1[2][(size_t)BB * HH];
__device__ float g_c1[(size_t)BB * HH];
__device__ float g_c2[(size_t)BB * HH];
__device__ float g_hist[(size_t)(TT + 1) * BB * HH];   // h2 history, slot 0 = initial
__device__ float g_xr[(size_t)BB * TT * II];           // tf32-rounded x
__device__ __align__(256) float g_wp1[(size_t)16 * 36 * 256 * 36];  // packed layer1 W
__device__ __align__(256) float g_wp2[(size_t)16 * 64 * 256 * 36];  // packed layer2 W

__device__ __forceinline__ uint32_t f2tf(float x) {
    uint32_t u;
    asm("cvt.rna.tf32.f32 %0, %1;" : "=r"(u) : "f"(x));
    return u;
}
__device__ __forceinline__ float rnaf(float x) { return __uint_as_float(f2tf(x)); }
__device__ __forceinline__ float sigf(float x) { return 1.f / (1.f + expf(-x)); }

__device__ __forceinline__ void mma8(float* c, uint32_t a0, uint32_t a1, uint32_t a2, uint32_t a3,
                                     uint32_t b0, uint32_t b1) {
    asm volatile(
        "mma.sync.aligned.m16n8k8.row.col.f32.tf32.tf32.f32 "
        "{%0,%1,%2,%3},{%4,%5,%6,%7},{%8,%9},{%0,%1,%2,%3};"
        : "+f"(c[0]), "+f"(c[1]), "+f"(c[2]), "+f"(c[3])
        : "r"(a0), "r"(a1), "r"(a2), "r"(a3), "r"(b0), "r"(b1));
}

__device__ __forceinline__ uint32_t s2u(const void* p) {
    uint32_t a;
    asm("{ .reg .u64 t; cvta.to.shared.u64 t, %1; cvt.u32.u64 %0, t; }" : "=r"(a) : "l"(p));
    return a;
}
__device__ __forceinline__ void cpa16(uint32_t d, const void* s) {
    asm volatile("cp.async.cg.shared.global [%0], [%1], 16;" :: "r"(d), "l"(s));
}
#define CP_COMMIT() asm volatile("cp.async.commit_group;" ::: "memory")
#define CP_WAIT2()  asm volatile("cp.async.wait_group 2;" ::: "memory")

// ---------------------------------------------------------------------------
// Prep kernels (run once, negligible cost)
// ---------------------------------------------------------------------------
__global__ void round_kernel(const float* __restrict__ in, float* __restrict__ out, size_t n) {
    size_t stride = (size_t)gridDim.x * blockDim.x;
    for (size_t i = (size_t)blockIdx.x * blockDim.x + threadIdx.x; i < n; i += stride)
        out[i] = rnaf(in[i]);
}

// Pack W into [tile_n][s][l=256][36] smem-image, gate-permuted, tf32-rounded.
__global__ void pack_w_kernel(const float* __restrict__ Wih, int ldwi, int Ki,
                              const float* __restrict__ Whh,
                              float* __restrict__ out, int S) {
    size_t total = (size_t)16 * S * 256 * 36;
    size_t stride = (size_t)gridDim.x * blockDim.x;
    for (size_t idx = (size_t)blockIdx.x * blockDim.x + threadIdx.x; idx < total; idx += stride) {
        int j = (int)(idx % 36); size_t r = idx / 36;
        int l = (int)(r % 256); r /= 256;
        int s = (int)(r % S);   int tn = (int)(r / S);
        float v = 0.f;
        if (j < 32) {
            int k = s * 32 + j;
            int wr = (l >> 6) * HH + tn * 64 + (l & 63);
            float src = (k < Ki) ? Wih[(size_t)wr * ldwi + k]
                                 : Whh[(size_t)wr * HH + (k - Ki)];
            v = rnaf(src);
        }
        out[idx] = v;
    }
}

// ---------------------------------------------------------------------------
// Gate GEMM + fused LSTM cell. Tile 128x256 (gate-permuted N), 256 threads.
// A = [A1 (s1 stages) | A2 (rest)], K staged 32 wide, cp.async 3-deep pipeline.
// ---------------------------------------------------------------------------
struct GP {
    const float* A1; long lda1; int s1;
    const float* A2;               // lda = HH
    int S;                         // total stages
    const float* Wp;               // packed weights base
    const float* b1; const float* b2;
    float* H; float* C;
};

#define SM_BUF 55296               // per pipe stage: A 128*36*4 + B 256*36*4
#define SM_TOTAL (1024 + 3 * SM_BUF)

__device__ __forceinline__ void gate_body(const GP& p, int bid, char* smem) {
    const uint32_t sb = s2u(smem);
    float* bias = (float*)smem;
    const int tid = threadIdx.x, lane = tid & 31, wid = tid >> 5;
    const int gid = lane >> 2, tig = lane & 3;
    const int tile_m = bid >> 4, tile_n = bid & 15;
    const int bm = tile_m * 128;
    const int mwarp = (wid >> 2) * 64, nwarp = (wid & 3) * 64;

    {   // summed permuted bias
        int wr = (tid >> 6) * HH + tile_n * 64 + (tid & 63);
        bias[tid] = p.b1[wr] + p.b2[wr];
    }

    float acc[4][8][4];
#pragma unroll
    for (int a = 0; a < 4; a++)
#pragma unroll
        for (int b = 0; b < 8; b++)
#pragma unroll
            for (int c = 0; c < 4; c++) acc[a][b][c] = 0.f;

    const float* wp_base = p.Wp + (size_t)tile_n * p.S * (256 * 36);

    auto load = [&](int s) {
        const int buf = s % 3;
        const float* A; long lda; int kk;
        if (s < p.s1) { A = p.A1; lda = p.lda1; kk = s * 32; }
        else          { A = p.A2; lda = HH;     kk = (s - p.s1) * 32; }
        const uint32_t ab = sb + 1024 + buf * SM_BUF;
        const float* Arow = A + (size_t)bm * lda + kk;
#pragma unroll
        for (int i = 0; i < 4; i++) {
            int c = tid + i * 256, row = c >> 3, kc = c & 7;
            cpa16(ab + row * 144 + kc * 16, Arow + (size_t)row * lda + kc * 4);
        }
        const uint32_t bb = ab + 18432;
        const float* Ws = wp_base + (size_t)s * (256 * 36);
#pragma unroll
        for (int i = 0; i < 9; i++) {
            int c = tid + i * 256;
            cpa16(bb + c * 16, Ws + c * 4);
        }
    };

    // prologue: stages 0,1,2
    load(0); CP_COMMIT();
    load(1); CP_COMMIT();
    load(2); CP_COMMIT();

    for (int s = 0; s < p.S; s++) {
        CP_WAIT2();
        __syncthreads();
        {   // MMA on buf s%3
            const uint32_t* As = (const uint32_t*)(smem + 1024 + (s % 3) * SM_BUF);
            const uint32_t* Bs = As + 128 * 36;
#pragma unroll
            for (int ks = 0; ks < 4; ks++) {
                int kk = ks * 8 + tig;
                uint32_t bf[8][2];
#pragma unroll
                for (int n = 0; n < 8; n++) {
                    int col = nwarp + n * 8 + gid;
                    bf[n][0] = Bs[col * 36 + kk];
                    bf[n][1] = Bs[col * 36 + kk + 4];
                }
#pragma unroll
                for (int mi = 0; mi < 4; mi++) {
                    int row = mwarp + mi * 16 + gid;
                    uint32_t a0 = As[row * 36 + kk];
                    uint32_t a1 = As[(row + 8) * 36 + kk];
                    uint32_t a2 = As[row * 36 + kk + 4];
                    uint32_t a3 = As[(row + 8) * 36 + kk + 4];
#pragma unroll
                    for (int n = 0; n < 8; n++)
                        mma8(acc[mi][n], a0, a1, a2, a3, bf[n][0], bf[n][1]);
                }
            }
        }
        __syncthreads();
        if (s + 3 < p.S) load(s + 3);
        CP_COMMIT();   // pad group to keep wait count uniform
    }

    // Epilogue: two 64-row phases staged through smem
    float* stage = (float*)(smem + 1024);
#pragma unroll
    for (int ph = 0; ph < 2; ph++) {
        if ((wid >> 2) == ph) {
#pragma unroll
            for (int mi = 0; mi < 4; mi++)
#pragma unroll
                for (int n = 0; n < 8; n++) {
                    int r0 = mi * 16 + gid, c = nwarp + n * 8 + 2 * tig;
                    stage[r0 * 260 + c]           = acc[mi][n][0];
                    stage[r0 * 260 + c + 1]       = acc[mi][n][1];
                    stage[(r0 + 8) * 260 + c]     = acc[mi][n][2];
                    stage[(r0 + 8) * 260 + c + 1] = acc[mi][n][3];
                }
        }
        __syncthreads();
        {
            int r = tid >> 2, u0 = (tid & 3) * 16;
            int m = bm + ph * 64 + r;
            float* crow = p.C + (size_t)m * HH + tile_n * 64;
            float* hrow = p.H + (size_t)m * HH + tile_n * 64;
#pragma unroll
            for (int jb = 0; jb < 4; jb++) {
                float4 cv = *(float4*)(crow + u0 + jb * 4);
                float4 hv;
                float* cvp = (float*)&cv;
                float* hvp = (float*)&hv;
#pragma unroll
                for (int e = 0; e < 4; e++) {
                    int u = u0 + jb * 4 + e;
                    float iv = sigf(stage[r * 260 + u] + bias[u]);
                    float fv = sigf(stage[r * 260 + 64 + u] + bias[64 + u]);
                    float gv = tanhf(stage[r * 260 + 128 + u] + bias[128 + u]);
                    float ov = sigf(stage[r * 260 + 192 + u] + bias[192 + u]);
                    float cn = fv * cvp[e] + iv * gv;
                    cvp[e] = cn;
                    hvp[e] = rnaf(ov * tanhf(cn));  // h kept tf32-clean for next GEMM
                }
                *(float4*)(crow + u0 + jb * 4) = cv;
                *(float4*)(hrow + u0 + jb * 4) = hv;
            }
        }
        __syncthreads();
    }
}

__global__ __launch_bounds__(256, 1)
void step_gemm(GP pa, GP pb, int nb_a) {
    extern __shared__ __align__(16) char smem[];
    if ((int)blockIdx.x < nb_a) gate_body(pa, blockIdx.x, smem);
    else                        gate_body(pb, blockIdx.x - nb_a, smem);
}

// ---------------------------------------------------------------------------
// Batched fc over the whole h2 history (unchanged from R3, works well enough)
// ---------------------------------------------------------------------------
__global__ __launch_bounds__(256, 1)
void fc_gemm(const float* __restrict__ A, const float* __restrict__ W,
             const float* __restrict__ bias_g, float* __restrict__ out)
{
    extern __shared__ __align__(16) char smem[];
    constexpr int OFF_A = 1024;
    constexpr int ASZ = 128 * 36 * 4;
    constexpr int OFF_B = OFF_A + 2 * ASZ;

    float* bias = (float*)smem;
    const int tid = threadIdx.x, lane = tid & 31, wid = tid >> 5;
    const int gid = lane >> 2, tig = lane & 3;
    const int bm = blockIdx.x * 128;
    const int mwarp = (wid >> 2) * 64, nwarp = (wid & 3) * 32;

    if (tid < II) bias[tid] = bias_g[tid];

    float acc[4][4][4];
#pragma unroll
    for (int a = 0; a < 4; a++)
#pragma unroll
        for (int b = 0; b < 4; b++)
#pragma unroll
            for (int c = 0; c < 4; c++) acc[a][b][c] = 0.f;

    float4 pa[4], pb[4];
    auto ldg = [&](int s) {
        int kk = s * 32;
#pragma unroll
        for (int i = 0; i < 4; i++) {
            int f = tid + i * 256, row = f >> 3, kc = f & 7;
            pa[i] = *(const float4*)(A + (size_t)(bm + row) * HH + kk + kc * 4);
            pb[i] = *(const float4*)(W + (size_t)row * HH + kk + kc * 4);
        }
    };
    auto sts = [&](int buf) {
        uint32_t* As = (uint32_t*)(smem + OFF_A + buf * ASZ);
        uint32_t* Bs = (uint32_t*)(smem + OFF_B + buf * ASZ);
#pragma unroll
        for (int i = 0; i < 4; i++) {
            int f = tid + i * 256, row = f >> 3, kc = f & 7;
            uint4 va = {f2tf(pa[i].x), f2tf(pa[i].y), f2tf(pa[i].z), f2tf(pa[i].w)};
            *(uint4*)(As + row * 36 + kc * 4) = va;
            uint4 vb = {f2tf(pb[i].x), f2tf(pb[i].y), f2tf(pb[i].z), f2tf(pb[i].w)};
            *(uint4*)(Bs + row * 36 + kc * 4) = vb;
        }
    };
    auto domma = [&](int buf) {
        const uint32_t* As = (const uint32_t*)(smem + OFF_A + buf * ASZ);
        const uint32_t* Bs = (const uint32_t*)(smem + OFF_B + buf * ASZ);
#pragma unroll
        for (int ks = 0; ks < 4; ks++) {
            int kk = ks * 8 + tig;
            uint32_t bf[4][2];
#pragma unroll
            for (int n = 0; n < 4; n++) {
                int col = nwarp + n * 8 + gid;
                bf[n][0] = Bs[col * 36 + kk];
                bf[n][1] = Bs[col * 36 + kk + 4];
            }
#pragma unroll
            for (int mi = 0; mi < 4; mi++) {
                int row = mwarp + mi * 16 + gid;
                uint32_t a0 = As[row * 36 + kk];
                uint32_t a1 = As[(row + 8) * 36 + kk];
                uint32_t a2 = As[row * 36 + kk + 4];
                uint32_t a3 = As[(row + 8) * 36 + kk + 4];
#pragma unroll
                for (int n = 0; n < 4; n++)
                    mma8(acc[mi][n], a0, a1, a2, a3, bf[n][0], bf[n][1]);
            }
        }
    };

    ldg(0); sts(0); __syncthreads();
    for (int s = 0; s < 32; s++) {
        int buf = s & 1;
        if (s + 1 < 32) ldg(s + 1);
        domma(buf);
        if (s + 1 < 32) sts(buf ^ 1);
        __syncthreads();
    }

#pragma unroll
    for (int mi = 0; mi < 4; mi++) {
        int r0 = bm + mwarp + mi * 16 + gid;
#pragma unroll
        for (int half = 0; half < 2; half++) {
            int m = r0 + half * 8;
            size_t orow = ((size_t)(m & (BB - 1)) * TT + (m >> 11)) * II;
#pragma unroll
            for (int n = 0; n < 4; n++) {
                int c = nwarp + n * 8 + 2 * tig;
                float2 v;
                v.x = acc[mi][n][half * 2 + 0] + bias[c];
                v.y = acc[mi][n][half * 2 + 1] + bias[c + 1];
                *(float2*)(out + orow + c) = v;
            }
        }
    }
}

// ---------------------------------------------------------------------------
extern "C" void kernel_launch(void* const* d_in, const int* in_sizes, int n_in,
                              void* d_out, int out_size)
{
    const float* x     = (const float*)d_in[0];
    const float* h1_in = (const float*)d_in[1];
    const float* c1_in = (const float*)d_in[2];
    const float* h2_in = (const float*)d_in[3];
    const float* c2_in = (const float*)d_in[4];
    const float* w_ih1 = (const float*)d_in[5];
    const float* w_hh1 = (const float*)d_in[6];
    const float* b_ih1 = (const float*)d_in[7];
    const float* b_hh1 = (const float*)d_in[8];
    const float* w_ih2 = (const float*)d_in[9];
    const float* w_hh2 = (const float*)d_in[10];
    const float* b_ih2 = (const float*)d_in[11];
    const float* b_hh2 = (const float*)d_in[12];
    const float* fc_w  = (const float*)d_in[13];
    const float* fc_b  = (const float*)d_in[14];
    float* out = (float*)d_out;

    float *h1p, *c1p, *c2p, *histp, *xrp, *wp1, *wp2;
    cudaGetSymbolAddress((void**)&h1p, g_h1);
    cudaGetSymbolAddress((void**)&c1p, g_c1);
    cudaGetSymbolAddress((void**)&c2p, g_c2);
    cudaGetSymbolAddress((void**)&histp, g_hist);
    cudaGetSymbolAddress((void**)&xrp, g_xr);
    cudaGetSymbolAddress((void**)&wp1, g_wp1);
    cudaGetSymbolAddress((void**)&wp2, g_wp2);

    const size_t SN = (size_t)BB * HH;
    const size_t SB = SN * sizeof(float);

    // Prep: tf32-round inputs; pack weights
    round_kernel<<<1024, 256>>>(x, xrp, (size_t)BB * TT * II);
    round_kernel<<<256, 256>>>(h1_in, h1p, SN);            // H1[0] in buf 0
    round_kernel<<<256, 256>>>(h2_in, histp, SN);          // H2[0] in slot 0
    cudaMemcpyAsync(c1p, c1_in, SB, cudaMemcpyDeviceToDevice);
    cudaMemcpyAsync(c2p, c2_in, SB, cudaMemcpyDeviceToDevice);
    pack_w_kernel<<<2048, 256>>>(w_ih1, II, II, w_hh1, wp1, 36);
    pack_w_kernel<<<2048, 256>>>(w_ih2, HH, HH, w_hh2, wp2, 64);

    cudaFuncSetAttribute(step_gemm, cudaFuncAttributeMaxDynamicSharedMemorySize, SM_TOTAL);
    constexpr int SMEM_FC = 1024 + 4 * (128 * 36 * 4);
    cudaFuncSetAttribute(fc_gemm, cudaFuncAttributeMaxDynamicSharedMemorySize, SMEM_FC);

    auto mkL1 = [&](int t) {  // layer1 step t: reads H1[t], x_t -> writes H1[t+1]
        GP p;
        p.A1 = xrp + (size_t)t * II; p.lda1 = TT * II; p.s1 = 4;
        p.A2 = h1p + (size_t)(t & 1) * SN;
        p.S = 36; p.Wp = wp1; p.b1 = b_ih1; p.b2 = b_hh1;
        p.H = h1p + (size_t)((t + 1) & 1) * SN; p.C = c1p;
        return p;
    };
    auto mkL2 = [&](int t) {  // layer2 step t: reads H1[t+1], H2[t] -> writes H2[t+1]
        GP p;
        p.A1 = h1p + (size_t)((t + 1) & 1) * SN; p.lda1 = HH; p.s1 = 32;
        p.A2 = histp + (size_t)t * SN;
        p.S = 64; p.Wp = wp2; p.b1 = b_ih2; p.b2 = b_hh2;
        p.H = histp + (size_t)(t + 1) * SN; p.C = c2p;
        return p;
    };

    // layer1(0) solo; then fused layer2(t)+layer1(t+1); then layer2(63) solo
    {
        GP p = mkL1(0);
        step_gemm<<<256, 256, SM_TOTAL>>>(p, p, 256);
    }
    for (int t = 0; t < TT - 1; t++) {
        GP p2 = mkL2(t), p1 = mkL1(t + 1);
        step_gemm<<<512, 256, SM_TOTAL>>>(p2, p1, 256);
    }
    {
        GP p = mkL2(TT - 1);
        step_gemm<<<256, 256, SM_TOTAL>>>(p, p, 256);
    }

    // Batched fc over all timesteps
    fc_gemm<<<1024, 256, SMEM_FC>>>(histp + SN, fc_w, fc_b, out);

    // Final states: output_seq ‖ h1 ‖ c1 ‖ h2 ‖ c2
    float* tail = out + (size_t)BB * TT * II;
    cudaMemcpyAsync(tail + 0 * SN, h1p, SB, cudaMemcpyDeviceToDevice);  // H1[64] in buf 0
    cudaMemcpyAsync(tail + 1 * SN, c1p, SB, cudaMemcpyDeviceToDevice);
    cudaMemcpyAsync(tail + 2 * SN, histp + (size_t)TT * SN, SB, cudaMemcpyDeviceToDevice);
    cudaMemcpyAsync(tail + 3 * SN, c2p, SB, cudaMemcpyDeviceToDevice);
}

// round 5
// speedup vs baseline: 4.0966x; 1.1013x over previous
#include <cuda_runtime.h>
#include <cstdint>
#include <cstddef>

#define BB 2048
#define TT 64
#define II 128
#define HH 1024

// Static device scratch (no allocations allowed)
__device__ float g_h1[2][(size_t)BB * HH];
__device__ float g_c1[(size_t)BB * HH];
__device__ float g_c2[(size_t)BB * HH];
__device__ float g_hist[(size_t)(TT + 1) * BB * HH];   // h2 history, slot 0 = initial
__device__ float g_xr[(size_t)BB * TT * II];           // tf32-rounded x
__device__ __align__(256) float g_wp1[(size_t)16 * 36 * 256 * 36];  // packed layer1 W
__device__ __align__(256) float g_wp2[(size_t)16 * 64 * 256 * 36];  // packed layer2 W

__device__ __forceinline__ uint32_t f2tf(float x) {
    uint32_t u;
    asm("cvt.rna.tf32.f32 %0, %1;" : "=r"(u) : "f"(x));
    return u;
}
__device__ __forceinline__ float rnaf(float x) { return __uint_as_float(f2tf(x)); }
__device__ __forceinline__ float sigf(float x) { return 1.f / (1.f + expf(-x)); }

__device__ __forceinline__ void mma8(float* c, uint32_t a0, uint32_t a1, uint32_t a2, uint32_t a3,
                                     uint32_t b0, uint32_t b1) {
    asm volatile(
        "mma.sync.aligned.m16n8k8.row.col.f32.tf32.tf32.f32 "
        "{%0,%1,%2,%3},{%4,%5,%6,%7},{%8,%9},{%0,%1,%2,%3};"
        : "+f"(c[0]), "+f"(c[1]), "+f"(c[2]), "+f"(c[3])
        : "r"(a0), "r"(a1), "r"(a2), "r"(a3), "r"(b0), "r"(b1));
}

#define LDSM4(r0, r1, r2, r3, addr) \
    asm volatile("ldmatrix.sync.aligned.m8n8.x4.shared.b16 {%0,%1,%2,%3}, [%4];" \
                 : "=r"(r0), "=r"(r1), "=r"(r2), "=r"(r3) : "r"(addr))

__device__ __forceinline__ uint32_t s2u(const void* p) {
    uint32_t a;
    asm("{ .reg .u64 t; cvta.to.shared.u64 t, %1; cvt.u32.u64 %0, t; }" : "=r"(a) : "l"(p));
    return a;
}
__device__ __forceinline__ void cpa16(uint32_t d, const void* s) {
    asm volatile("cp.async.cg.shared.global [%0], [%1], 16;" :: "r"(d), "l"(s));
}
#define CP_COMMIT() asm volatile("cp.async.commit_group;" ::: "memory")
#define CP_WAIT1()  asm volatile("cp.async.wait_group 1;" ::: "memory")

// ---------------------------------------------------------------------------
// Prep kernels
// ---------------------------------------------------------------------------
__global__ void round_kernel(const float* __restrict__ in, float* __restrict__ out, size_t n) {
    size_t stride = (size_t)gridDim.x * blockDim.x;
    for (size_t i = (size_t)blockIdx.x * blockDim.x + threadIdx.x; i < n; i += stride)
        out[i] = rnaf(in[i]);
}

// Pack W into [tile_n][s][l=256][36] smem-image, gate-permuted, tf32-rounded.
__global__ void pack_w_kernel(const float* __restrict__ Wih, int ldwi, int Ki,
                              const float* __restrict__ Whh,
                              float* __restrict__ out, int S) {
    size_t total = (size_t)16 * S * 256 * 36;
    size_t stride = (size_t)gridDim.x * blockDim.x;
    for (size_t idx = (size_t)blockIdx.x * blockDim.x + threadIdx.x; idx < total; idx += stride) {
        int j = (int)(idx % 36); size_t r = idx / 36;
        int l = (int)(r % 256); r /= 256;
        int s = (int)(r % S);   int tn = (int)(r / S);
        float v = 0.f;
        if (j < 32) {
            int k = s * 32 + j;
            int wr = (l >> 6) * HH + tn * 64 + (l & 63);
            float src = (k < Ki) ? Wih[(size_t)wr * ldwi + k]
                                 : Whh[(size_t)wr * HH + (k - Ki)];
            v = rnaf(src);
        }
        out[idx] = v;
    }
}

// ---------------------------------------------------------------------------
// Gate GEMM + fused LSTM cell. Tile 128x256 (gate-permuted N), 512 threads.
// 16 warps in 4(m)x4(n) grid; each warp 32x64. ldmatrix operand feed.
// 2-deep cp.async pipeline, K staged 32 wide.
// ---------------------------------------------------------------------------
struct GP {
    const float* A1; long lda1; int s1;
    const float* A2;               // lda = HH
    int S;                         // total stages
    const float* Wp;               // packed weights base
    const float* b1; const float* b2;
    float* H; float* C;
};

#define SM_BUF 55296               // per stage: A 128*36*4 + B 256*36*4
#define SM_TOTAL (1024 + 2 * SM_BUF)

__device__ __forceinline__ void gate_body(const GP& p, int bid, char* smem) {
    const uint32_t sb = s2u(smem);
    float* bias = (float*)smem;
    const int tid = threadIdx.x, lane = tid & 31, wid = tid >> 5;
    const int tile_m = bid >> 4, tile_n = bid & 15;
    const int bm = tile_m * 128;
    const int wm = wid & 3, wn = wid >> 2;        // 4x4 warp grid
    const int mwarp = wm * 32, nwarp = wn * 64;

    if (tid < 256) {   // summed permuted bias
        int wr = (tid >> 6) * HH + tile_n * 64 + (tid & 63);
        bias[tid] = p.b1[wr] + p.b2[wr];
    }

    float acc[2][8][4];
#pragma unroll
    for (int a = 0; a < 2; a++)
#pragma unroll
        for (int b = 0; b < 8; b++)
#pragma unroll
            for (int c = 0; c < 4; c++) acc[a][b][c] = 0.f;

    const float* wp_base = p.Wp + (size_t)tile_n * p.S * (256 * 36);

    // Per-thread ldmatrix row offsets (bytes) within a buffer
    const uint32_t arow = (uint32_t)((mwarp + (lane & 7) + ((lane >> 3) & 1) * 8) * 144
                                     + (lane >> 4) * 16);
    const uint32_t brow = (uint32_t)((nwarp + (lane & 7) + (lane >> 4) * 8) * 144
                                     + ((lane >> 3) & 1) * 16);

    auto load = [&](int s) {
        const int buf = s & 1;
        const float* A; long lda; int kk;
        if (s < p.s1) { A = p.A1; lda = p.lda1; kk = s * 32; }
        else          { A = p.A2; lda = HH;     kk = (s - p.s1) * 32; }
        const uint32_t ab = sb + 1024 + buf * SM_BUF;
        const float* Arow = A + (size_t)bm * lda + kk;
#pragma unroll
        for (int i = 0; i < 2; i++) {   // 1024 granules, 512 threads
            int c = tid + i * 512, row = c >> 3, kc = c & 7;
            cpa16(ab + row * 144 + kc * 16, Arow + (size_t)row * lda + kc * 4);
        }
        const uint32_t bb2 = ab + 18432;
        const float* Ws = wp_base + (size_t)s * (256 * 36);
#pragma unroll
        for (int i = 0; i < 4; i++) {   // 2304 granules: 4 full rounds + half
            int c = tid + i * 512;
            cpa16(bb2 + c * 16, Ws + c * 4);
        }
        if (tid < 256) cpa16(bb2 + (tid + 2048) * 16, Ws + (size_t)(tid + 2048) * 4);
    };

    load(0); CP_COMMIT();
    if (p.S > 1) load(1);
    CP_COMMIT();

    for (int s = 0; s < p.S; s++) {
        CP_WAIT1();
        __syncthreads();
        {
            const int buf = s & 1;
            const uint32_t abase = sb + 1024 + buf * SM_BUF;
            const uint32_t bbase = abase + 18432;
#pragma unroll
            for (int ks = 0; ks < 4; ks++) {
                uint32_t af[2][4], bf[4][4];
#pragma unroll
                for (int mi = 0; mi < 2; mi++)
                    LDSM4(af[mi][0], af[mi][1], af[mi][2], af[mi][3],
                          abase + arow + mi * 2304 + ks * 32);
#pragma unroll
                for (int np = 0; np < 4; np++)
                    LDSM4(bf[np][0], bf[np][1], bf[np][2], bf[np][3],
                          bbase + brow + np * 2304 + ks * 32);
#pragma unroll
                for (int mi = 0; mi < 2; mi++)
#pragma unroll
                    for (int np = 0; np < 4; np++) {
                        mma8(acc[mi][2 * np],     af[mi][0], af[mi][1], af[mi][2], af[mi][3],
                             bf[np][0], bf[np][1]);
                        mma8(acc[mi][2 * np + 1], af[mi][0], af[mi][1], af[mi][2], af[mi][3],
                             bf[np][2], bf[np][3]);
                    }
            }
        }
        __syncthreads();
        if (s + 2 < p.S) load(s + 2);
        CP_COMMIT();
    }

    // Epilogue: two 64-row phases staged through smem (64 x 260 floats)
    float* stage = (float*)(smem + 1024);
    const int gid = lane >> 2, tig = lane & 3;
#pragma unroll
    for (int ph = 0; ph < 2; ph++) {
        if ((wm >> 1) == ph) {
#pragma unroll
            for (int mi = 0; mi < 2; mi++)
#pragma unroll
                for (int n = 0; n < 8; n++) {
                    int r0 = (wm & 1) * 32 + mi * 16 + gid;
                    int c = nwarp + n * 8 + 2 * tig;
                    stage[r0 * 260 + c]           = acc[mi][n][0];
                    stage[r0 * 260 + c + 1]       = acc[mi][n][1];
                    stage[(r0 + 8) * 260 + c]     = acc[mi][n][2];
                    stage[(r0 + 8) * 260 + c + 1] = acc[mi][n][3];
                }
        }
        __syncthreads();
        {
            int r = tid >> 3, u0 = (tid & 7) * 8;
            int m = bm + ph * 64 + r;
            float* crow = p.C + (size_t)m * HH + tile_n * 64;
            float* hrow = p.H + (size_t)m * HH + tile_n * 64;
#pragma unroll
            for (int jb = 0; jb < 2; jb++) {
                float4 cv = *(float4*)(crow + u0 + jb * 4);
                float4 hv;
                float* cvp = (float*)&cv;
                float* hvp = (float*)&hv;
#pragma unroll
                for (int e = 0; e < 4; e++) {
                    int u = u0 + jb * 4 + e;
                    float iv = sigf(stage[r * 260 + u] + bias[u]);
                    float fv = sigf(stage[r * 260 + 64 + u] + bias[64 + u]);
                    float gv = tanhf(stage[r * 260 + 128 + u] + bias[128 + u]);
                    float ov = sigf(stage[r * 260 + 192 + u] + bias[192 + u]);
                    float cn = fv * cvp[e] + iv * gv;
                    cvp[e] = cn;
                    hvp[e] = rnaf(ov * tanhf(cn));  // h kept tf32-clean for next GEMM
                }
                *(float4*)(crow + u0 + jb * 4) = cv;
                *(float4*)(hrow + u0 + jb * 4) = hv;
            }
        }
        __syncthreads();
    }
}

__global__ __launch_bounds__(512, 1)
void step_gemm(GP pa, GP pb, int nb_a) {
    extern __shared__ __align__(16) char smem[];
    if ((int)blockIdx.x < nb_a) gate_body(pa, blockIdx.x, smem);
    else                        gate_body(pb, blockIdx.x - nb_a, smem);
}

// ---------------------------------------------------------------------------
// Batched fc over the whole h2 history
// ---------------------------------------------------------------------------
__global__ __launch_bounds__(256, 1)
void fc_gemm(const float* __restrict__ A, const float* __restrict__ W,
             const float* __restrict__ bias_g, float* __restrict__ out)
{
    extern __shared__ __align__(16) char smem[];
    constexpr int OFF_A = 1024;
    constexpr int ASZ = 128 * 36 * 4;
    constexpr int OFF_B = OFF_A + 2 * ASZ;

    float* bias = (float*)smem;
    const int tid = threadIdx.x, lane = tid & 31, wid = tid >> 5;
    const int gid = lane >> 2, tig = lane & 3;
    const int bm = blockIdx.x * 128;
    const int mwarp = (wid >> 2) * 64, nwarp = (wid & 3) * 32;

    if (tid < II) bias[tid] = bias_g[tid];

    float acc[4][4][4];
#pragma unroll
    for (int a = 0; a < 4; a++)
#pragma unroll
        for (int b = 0; b < 4; b++)
#pragma unroll
            for (int c = 0; c < 4; c++) acc[a][b][c] = 0.f;

    float4 pa[4], pb[4];
    auto ldg = [&](int s) {
        int kk = s * 32;
#pragma unroll
        for (int i = 0; i < 4; i++) {
            int f = tid + i * 256, row = f >> 3, kc = f & 7;
            pa[i] = *(const float4*)(A + (size_t)(bm + row) * HH + kk + kc * 4);
            pb[i] = *(const float4*)(W + (size_t)row * HH + kk + kc * 4);
        }
    };
    auto sts = [&](int buf) {
        uint32_t* As = (uint32_t*)(smem + OFF_A + buf * ASZ);
        uint32_t* Bs = (uint32_t*)(smem + OFF_B + buf * ASZ);
#pragma unroll
        for (int i = 0; i < 4; i++) {
            int f = tid + i * 256, row = f >> 3, kc = f & 7;
            uint4 va = {f2tf(pa[i].x), f2tf(pa[i].y), f2tf(pa[i].z), f2tf(pa[i].w)};
            *(uint4*)(As + row * 36 + kc * 4) = va;
            uint4 vb = {f2tf(pb[i].x), f2tf(pb[i].y), f2tf(pb[i].z), f2tf(pb[i].w)};
            *(uint4*)(Bs + row * 36 + kc * 4) = vb;
        }
    };
    auto domma = [&](int buf) {
        const uint32_t abase = s2u(smem) + OFF_A + buf * ASZ;
        const uint32_t bbase = s2u(smem) + OFF_B + buf * ASZ;
        const uint32_t arow = (uint32_t)((mwarp + (lane & 7) + ((lane >> 3) & 1) * 8) * 144
                                         + (lane >> 4) * 16);
        const uint32_t brow = (uint32_t)((nwarp + (lane & 7) + (lane >> 4) * 8) * 144
                                         + ((lane >> 3) & 1) * 16);
#pragma unroll
        for (int ks = 0; ks < 4; ks++) {
            uint32_t af[4][4], bf[2][4];
#pragma unroll
            for (int mi = 0; mi < 4; mi++)
                LDSM4(af[mi][0], af[mi][1], af[mi][2], af[mi][3],
                      abase + arow + mi * 2304 + ks * 32);
#pragma unroll
            for (int np = 0; np < 2; np++)
                LDSM4(bf[np][0], bf[np][1], bf[np][2], bf[np][3],
                      bbase + brow + np * 2304 + ks * 32);
#pragma unroll
            for (int mi = 0; mi < 4; mi++)
#pragma unroll
                for (int np = 0; np < 2; np++) {
                    mma8(acc[mi][2 * np],     af[mi][0], af[mi][1], af[mi][2], af[mi][3],
                         bf[np][0], bf[np][1]);
                    mma8(acc[mi][2 * np + 1], af[mi][0], af[mi][1], af[mi][2], af[mi][3],
                         bf[np][2], bf[np][3]);
                }
        }
    };

    ldg(0); sts(0); __syncthreads();
    for (int s = 0; s < 32; s++) {
        int buf = s & 1;
        if (s + 1 < 32) ldg(s + 1);
        domma(buf);
        if (s + 1 < 32) sts(buf ^ 1);
        __syncthreads();
    }

#pragma unroll
    for (int mi = 0; mi < 4; mi++) {
        int r0 = bm + mwarp + mi * 16 + gid;
#pragma unroll
        for (int half = 0; half < 2; half++) {
            int m = r0 + half * 8;
            size_t orow = ((size_t)(m & (BB - 1)) * TT + (m >> 11)) * II;
#pragma unroll
            for (int n = 0; n < 4; n++) {
                int c = nwarp + n * 8 + 2 * tig;
                float2 v;
                v.x = acc[mi][n][half * 2 + 0] + bias[c];
                v.y = acc[mi][n][half * 2 + 1] + bias[c + 1];
                *(float2*)(out + orow + c) = v;
            }
        }
    }
}

// ---------------------------------------------------------------------------
extern "C" void kernel_launch(void* const* d_in, const int* in_sizes, int n_in,
                              void* d_out, int out_size)
{
    const float* x     = (const float*)d_in[0];
    const float* h1_in = (const float*)d_in[1];
    const float* c1_in = (const float*)d_in[2];
    const float* h2_in = (const float*)d_in[3];
    const float* c2_in = (const float*)d_in[4];
    const float* w_ih1 = (const float*)d_in[5];
    const float* w_hh1 = (const float*)d_in[6];
    const float* b_ih1 = (const float*)d_in[7];
    const float* b_hh1 = (const float*)d_in[8];
    const float* w_ih2 = (const float*)d_in[9];
    const float* w_hh2 = (const float*)d_in[10];
    const float* b_ih2 = (const float*)d_in[11];
    const float* b_hh2 = (const float*)d_in[12];
    const float* fc_w  = (const float*)d_in[13];
    const float* fc_b  = (const float*)d_in[14];
    float* out = (float*)d_out;

    float *h1p, *c1p, *c2p, *histp, *xrp, *wp1, *wp2;
    cudaGetSymbolAddress((void**)&h1p, g_h1);
    cudaGetSymbolAddress((void**)&c1p, g_c1);
    cudaGetSymbolAddress((void**)&c2p, g_c2);
    cudaGetSymbolAddress((void**)&histp, g_hist);
    cudaGetSymbolAddress((void**)&xrp, g_xr);
    cudaGetSymbolAddress((void**)&wp1, g_wp1);
    cudaGetSymbolAddress((void**)&wp2, g_wp2);

    const size_t SN = (size_t)BB * HH;
    const size_t SB = SN * sizeof(float);

    round_kernel<<<1024, 256>>>(x, xrp, (size_t)BB * TT * II);
    round_kernel<<<256, 256>>>(h1_in, h1p, SN);
    round_kernel<<<256, 256>>>(h2_in, histp, SN);
    cudaMemcpyAsync(c1p, c1_in, SB, cudaMemcpyDeviceToDevice);
    cudaMemcpyAsync(c2p, c2_in, SB, cudaMemcpyDeviceToDevice);
    pack_w_kernel<<<2048, 256>>>(w_ih1, II, II, w_hh1, wp1, 36);
    pack_w_kernel<<<2048, 256>>>(w_ih2, HH, HH, w_hh2, wp2, 64);

    cudaFuncSetAttribute(step_gemm, cudaFuncAttributeMaxDynamicSharedMemorySize, SM_TOTAL);
    constexpr int SMEM_FC = 1024 + 4 * (128 * 36 * 4);
    cudaFuncSetAttribute(fc_gemm, cudaFuncAttributeMaxDynamicSharedMemorySize, SMEM_FC);

    auto mkL1 = [&](int t) {
        GP p;
        p.A1 = xrp + (size_t)t * II; p.lda1 = TT * II; p.s1 = 4;
        p.A2 = h1p + (size_t)(t & 1) * SN;
        p.S = 36; p.Wp = wp1; p.b1 = b_ih1; p.b2 = b_hh1;
        p.H = h1p + (size_t)((t + 1) & 1) * SN; p.C = c1p;
        return p;
    };
    auto mkL2 = [&](int t) {
        GP p;
        p.A1 = h1p + (size_t)((t + 1) & 1) * SN; p.lda1 = HH; p.s1 = 32;
        p.A2 = histp + (size_t)t * SN;
        p.S = 64; p.Wp = wp2; p.b1 = b_ih2; p.b2 = b_hh2;
        p.H = histp + (size_t)(t + 1) * SN; p.C = c2p;
        return p;
    };

    {
        GP p = mkL1(0);
        step_gemm<<<256, 512, SM_TOTAL>>>(p, p, 256);
    }
    for (int t = 0; t < TT - 1; t++) {
        GP p2 = mkL2(t), p1 = mkL1(t + 1);
        step_gemm<<<512, 512, SM_TOTAL>>>(p2, p1, 256);
    }
    {
        GP p = mkL2(TT - 1);
        step_gemm<<<256, 512, SM_TOTAL>>>(p, p, 256);
    }

    fc_gemm<<<1024, 256, SMEM_FC>>>(histp + SN, fc_w, fc_b, out);

    float* tail = out + (size_t)BB * TT * II;
    cudaMemcpyAsync(tail + 0 * SN, h1p, SB, cudaMemcpyDeviceToDevice);
    cudaMemcpyAsync(tail + 1 * SN, c1p, SB, cudaMemcpyDeviceToDevice);
    cudaMemcpyAsync(tail + 2 * SN, histp + (size_t)TT * SN, SB, cudaMemcpyDeviceToDevice);
    cudaMemcpyAsync(tail + 3 * SN, c2p, SB, cudaMemcpyDeviceToDevice);
}

// round 6
// speedup vs baseline: 5.9583x; 1.4544x over previous
#include <cuda_runtime.h>
#include <cuda_fp16.h>
#include <cstdint>
#include <cstddef>

#define BB 2048
#define TT 64
#define II 128
#define HH 1024

// Static device scratch (no allocations allowed). States kept in fp16 (same
// 10-bit significand as the tf32 path used before); c states stay fp32.
__device__ __half g_h1[2][(size_t)BB * HH];
__device__ float  g_c1[(size_t)BB * HH];
__device__ float  g_c2[(size_t)BB * HH];
__device__ __half g_hist[(size_t)(TT + 1) * BB * HH];  // h2 history, slot 0 = initial
__device__ __half g_xh[(size_t)BB * TT * II];          // fp16-rounded x
__device__ __align__(256) __half g_wp1[(size_t)16 * 36 * 256 * 40];  // packed layer1 W
__device__ __align__(256) __half g_wp2[(size_t)16 * 64 * 256 * 40];  // packed layer2 W
__device__ __align__(256) __half g_fcw[(size_t)II * HH];             // fp16 fc W

__device__ __forceinline__ float sigf(float x) { return 1.f / (1.f + expf(-x)); }

__device__ __forceinline__ void mma16(float* c, const uint32_t* a, uint32_t b0, uint32_t b1) {
    asm volatile(
        "mma.sync.aligned.m16n8k16.row.col.f32.f16.f16.f32 "
        "{%0,%1,%2,%3},{%4,%5,%6,%7},{%8,%9},{%0,%1,%2,%3};"
        : "+f"(c[0]), "+f"(c[1]), "+f"(c[2]), "+f"(c[3])
        : "r"(a[0]), "r"(a[1]), "r"(a[2]), "r"(a[3]), "r"(b0), "r"(b1));
}

#define LDSM4(r, addr) \
    asm volatile("ldmatrix.sync.aligned.m8n8.x4.shared.b16 {%0,%1,%2,%3}, [%4];" \
                 : "=r"((r)[0]), "=r"((r)[1]), "=r"((r)[2]), "=r"((r)[3]) : "r"(addr))

__device__ __forceinline__ uint32_t s2u(const void* p) {
    uint32_t a;
    asm("{ .reg .u64 t; cvta.to.shared.u64 t, %1; cvt.u32.u64 %0, t; }" : "=r"(a) : "l"(p));
    return a;
}
__device__ __forceinline__ void cpa16(uint32_t d, const void* s) {
    asm volatile("cp.async.cg.shared.global [%0], [%1], 16;" :: "r"(d), "l"(s));
}
#define CP_COMMIT() asm volatile("cp.async.commit_group;" ::: "memory")
#define CP_WAIT2()  asm volatile("cp.async.wait_group 2;" ::: "memory")

// ---------------------------------------------------------------------------
// Prep kernels
// ---------------------------------------------------------------------------
__global__ void round_h_kernel(const float* __restrict__ in, __half* __restrict__ out, size_t n) {
    size_t stride = (size_t)gridDim.x * blockDim.x;
    for (size_t i = (size_t)blockIdx.x * blockDim.x + threadIdx.x; i < n; i += stride)
        out[i] = __float2half_rn(in[i]);
}
__global__ void h2f_kernel(const __half* __restrict__ in, float* __restrict__ out, size_t n) {
    size_t stride = (size_t)gridDim.x * blockDim.x;
    for (size_t i = (size_t)blockIdx.x * blockDim.x + threadIdx.x; i < n; i += stride)
        out[i] = __half2float(in[i]);
}

// Pack W into [tile_n][s][l=256][40] fp16 smem-image (stride 40 halves = 80B),
// gate-permuted.
__global__ void pack_w_kernel(const float* __restrict__ Wih, int ldwi, int Ki,
                              const float* __restrict__ Whh,
                              __half* __restrict__ out, int S) {
    size_t total = (size_t)16 * S * 256 * 40;
    size_t stride = (size_t)gridDim.x * blockDim.x;
    for (size_t idx = (size_t)blockIdx.x * blockDim.x + threadIdx.x; idx < total; idx += stride) {
        int j = (int)(idx % 40); size_t r = idx / 40;
        int l = (int)(r % 256); r /= 256;
        int s = (int)(r % S);   int tn = (int)(r / S);
        float v = 0.f;
        if (j < 32) {
            int k = s * 32 + j;
            int wr = (l >> 6) * HH + tn * 64 + (l & 63);
            v = (k < Ki) ? Wih[(size_t)wr * ldwi + k]
                         : Whh[(size_t)wr * HH + (k - Ki)];
        }
        out[idx] = __float2half_rn(v);
    }
}

// ---------------------------------------------------------------------------
// Gate GEMM + fused LSTM cell. Tile 128x256 (gate-permuted N), 512 threads.
// 16 warps in 4(m)x4(n) grid; each warp 32x64. fp16 m16n8k16, ldmatrix feed.
// 3-deep cp.async pipeline, K staged 32 wide. Rows padded to 80B (bank-clean,
// 16B-aligned).
// ---------------------------------------------------------------------------
struct GP {
    const __half* A1; long lda1; int s1;
    const __half* A2;              // lda = HH
    int S;                         // total K stages
    const __half* Wp;              // packed weights base
    const float* b1; const float* b2;
    __half* H; float* C;
};

#define SM_BUF 30720               // per stage: A 128*80 + B 256*80 bytes
#define SM_TOTAL (1024 + 3 * SM_BUF)

__device__ __forceinline__ void gate_body(const GP& p, int bid, char* smem) {
    const uint32_t sb = s2u(smem);
    float* bias = (float*)smem;
    const int tid = threadIdx.x, lane = tid & 31, wid = tid >> 5;
    const int tile_m = bid >> 4, tile_n = bid & 15;
    const int bm = tile_m * 128;
    const int wm = wid & 3, wn = wid >> 2;        // 4x4 warp grid
    const int mwarp = wm * 32, nwarp = wn * 64;

    if (tid < 256) {   // summed permuted bias
        int wr = (tid >> 6) * HH + tile_n * 64 + (tid & 63);
        bias[tid] = p.b1[wr] + p.b2[wr];
    }

    float acc[2][8][4];
#pragma unroll
    for (int a = 0; a < 2; a++)
#pragma unroll
        for (int b = 0; b < 8; b++)
#pragma unroll
            for (int c = 0; c < 4; c++) acc[a][b][c] = 0.f;

    const __half* wp_base = p.Wp + (size_t)tile_n * p.S * (256 * 40);

    // ldmatrix per-thread offsets (bytes) within a buffer, 80B row stride
    const uint32_t arow = (uint32_t)((mwarp + (lane & 7) + ((lane >> 3) & 1) * 8) * 80
                                     + (lane >> 4) * 16);
    const uint32_t brow = (uint32_t)((nwarp + (lane & 7) + (lane >> 4) * 8) * 80
                                     + ((lane >> 3) & 1) * 16);

    auto load = [&](int s) {
        const int buf = s % 3;
        const __half* A; long lda; int kk;
        if (s < p.s1) { A = p.A1; lda = p.lda1; kk = s * 32; }
        else          { A = p.A2; lda = HH;     kk = (s - p.s1) * 32; }
        const uint32_t ab = sb + 1024 + buf * SM_BUF;
        const __half* Arow = A + (size_t)bm * lda + kk;
        {   // A: 128 rows x 4 granules = 512 (one per thread)
            int row = tid >> 2, kc = tid & 3;
            cpa16(ab + row * 80 + kc * 16, Arow + (size_t)row * lda + kc * 8);
        }
        const uint32_t bb2 = ab + 10240;
        const __half* Ws = wp_base + (size_t)s * (256 * 40);
#pragma unroll
        for (int i = 0; i < 2; i++) {   // B: 256 rows x 4 granules = 1024
            int c = tid + i * 512, row = c >> 2, kc = c & 3;
            cpa16(bb2 + row * 80 + kc * 16, Ws + row * 40 + kc * 8);
        }
    };

    load(0); CP_COMMIT();
    load(1); CP_COMMIT();
    load(2); CP_COMMIT();

    for (int s = 0; s < p.S; s++) {
        CP_WAIT2();
        __syncthreads();
        {
            const uint32_t abase = sb + 1024 + (s % 3) * SM_BUF;
            const uint32_t bbase = abase + 10240;
#pragma unroll
            for (int kc = 0; kc < 2; kc++) {   // two k16 chunks per K32 stage
                uint32_t af[2][4], bf[4][4];
#pragma unroll
                for (int mi = 0; mi < 2; mi++)
                    LDSM4(af[mi], abase + arow + mi * 1280 + kc * 32);
#pragma unroll
                for (int nb = 0; nb < 4; nb++)
                    LDSM4(bf[nb], bbase + brow + nb * 1280 + kc * 32);
#pragma unroll
                for (int mi = 0; mi < 2; mi++)
#pragma unroll
                    for (int nb = 0; nb < 4; nb++) {
                        mma16(acc[mi][2 * nb],     af[mi], bf[nb][0], bf[nb][1]);
                        mma16(acc[mi][2 * nb + 1], af[mi], bf[nb][2], bf[nb][3]);
                    }
            }
        }
        __syncthreads();
        if (s + 3 < p.S) load(s + 3);
        CP_COMMIT();
    }

    // Epilogue: two 64-row phases staged through smem (64 x 260 floats)
    float* stage = (float*)(smem + 1024);
    const int gid = lane >> 2, tig = lane & 3;
#pragma unroll
    for (int ph = 0; ph < 2; ph++) {
        if ((wm >> 1) == ph) {
#pragma unroll
            for (int mi = 0; mi < 2; mi++)
#pragma unroll
                for (int n = 0; n < 8; n++) {
                    int r0 = (wm & 1) * 32 + mi * 16 + gid;
                    int c = nwarp + n * 8 + 2 * tig;
                    stage[r0 * 260 + c]           = acc[mi][n][0];
                    stage[r0 * 260 + c + 1]       = acc[mi][n][1];
                    stage[(r0 + 8) * 260 + c]     = acc[mi][n][2];
                    stage[(r0 + 8) * 260 + c + 1] = acc[mi][n][3];
                }
        }
        __syncthreads();
        {
            int r = tid >> 3, u0 = (tid & 7) * 8;
            int m = bm + ph * 64 + r;
            float* crow = p.C + (size_t)m * HH + tile_n * 64;
            __half* hrow = p.H + (size_t)m * HH + tile_n * 64;
#pragma unroll
            for (int jb = 0; jb < 2; jb++) {
                float4 cv = *(float4*)(crow + u0 + jb * 4);
                float* cvp = (float*)&cv;
                __half hv[4];
#pragma unroll
                for (int e = 0; e < 4; e++) {
                    int u = u0 + jb * 4 + e;
                    float iv = sigf(stage[r * 260 + u] + bias[u]);
                    float fv = sigf(stage[r * 260 + 64 + u] + bias[64 + u]);
                    float gv = tanhf(stage[r * 260 + 128 + u] + bias[128 + u]);
                    float ov = sigf(stage[r * 260 + 192 + u] + bias[192 + u]);
                    float cn = fv * cvp[e] + iv * gv;
                    cvp[e] = cn;
                    hv[e] = __float2half_rn(ov * tanhf(cn));
                }
                *(float4*)(crow + u0 + jb * 4) = cv;
                *(uint2*)(hrow + u0 + jb * 4) = *(uint2*)hv;
            }
        }
        __syncthreads();
    }
}

__global__ __launch_bounds__(512, 1)
void step_gemm(GP pa, GP pb, int nb_a) {
    extern __shared__ __align__(16) char smem[];
    if ((int)blockIdx.x < nb_a) gate_body(pa, blockIdx.x, smem);
    else                        gate_body(pb, blockIdx.x - nb_a, smem);
}

// ---------------------------------------------------------------------------
// Batched fc over the whole h2 history (fp16 operands, 256 threads, 8 warps).
// Tile 128(m) x 128(n); warps: 2(m)x4(n), each 64x32.
// ---------------------------------------------------------------------------
#define SM_BUF_FC 20480            // A 128*80 + B 128*80
#define SM_TOTAL_FC (1024 + 3 * SM_BUF_FC)

__global__ __launch_bounds__(256, 1)
void fc_gemm(const __half* __restrict__ A, const __half* __restrict__ W,
             const float* __restrict__ bias_g, float* __restrict__ out)
{
    extern __shared__ __align__(16) char smem[];
    const uint32_t sb = s2u(smem);
    float* bias = (float*)smem;
    const int tid = threadIdx.x, lane = tid & 31, wid = tid >> 5;
    const int gid = lane >> 2, tig = lane & 3;
    const int bm = blockIdx.x * 128;
    const int mwarp = (wid >> 2) * 64, nwarp = (wid & 3) * 32;

    if (tid < II) bias[tid] = bias_g[tid];

    float acc[4][4][4];
#pragma unroll
    for (int a = 0; a < 4; a++)
#pragma unroll
        for (int b = 0; b < 4; b++)
#pragma unroll
            for (int c = 0; c < 4; c++) acc[a][b][c] = 0.f;

    const uint32_t arow = (uint32_t)((mwarp + (lane & 7) + ((lane >> 3) & 1) * 8) * 80
                                     + (lane >> 4) * 16);
    const uint32_t brow = (uint32_t)((nwarp + (lane & 7) + (lane >> 4) * 8) * 80
                                     + ((lane >> 3) & 1) * 16);

    auto load = [&](int s) {
        const int buf = s % 3;
        const uint32_t ab = sb + 1024 + buf * SM_BUF_FC;
        const uint32_t bb2 = ab + 10240;
        int kk = s * 32;
#pragma unroll
        for (int i = 0; i < 2; i++) {   // A: 512 granules
            int c = tid + i * 256, row = c >> 2, kc = c & 3;
            cpa16(ab + row * 80 + kc * 16, A + (size_t)(bm + row) * HH + kk + kc * 8);
        }
#pragma unroll
        for (int i = 0; i < 2; i++) {   // B: 512 granules
            int c = tid + i * 256, row = c >> 2, kc = c & 3;
            cpa16(bb2 + row * 80 + kc * 16, W + (size_t)row * HH + kk + kc * 8);
        }
    };

    load(0); CP_COMMIT();
    load(1); CP_COMMIT();
    load(2); CP_COMMIT();

    for (int s = 0; s < 32; s++) {
        CP_WAIT2();
        __syncthreads();
        {
            const uint32_t abase = sb + 1024 + (s % 3) * SM_BUF_FC;
            const uint32_t bbase = abase + 10240;
#pragma unroll
            for (int kc = 0; kc < 2; kc++) {
                uint32_t af[4][4], bf[2][4];
#pragma unroll
                for (int mi = 0; mi < 4; mi++)
                    LDSM4(af[mi], abase + arow + mi * 1280 + kc * 32);
#pragma unroll
                for (int nb = 0; nb < 2; nb++)
                    LDSM4(bf[nb], bbase + brow + nb * 1280 + kc * 32);
#pragma unroll
                for (int mi = 0; mi < 4; mi++)
#pragma unroll
                    for (int nb = 0; nb < 2; nb++) {
                        mma16(acc[mi][2 * nb],     af[mi], bf[nb][0], bf[nb][1]);
                        mma16(acc[mi][2 * nb + 1], af[mi], bf[nb][2], bf[nb][3]);
                    }
            }
        }
        __syncthreads();
        if (s + 3 < 32) load(s + 3);
        CP_COMMIT();
    }

    // Epilogue: scatter rows to out[b][t][:]
#pragma unroll
    for (int mi = 0; mi < 4; mi++) {
        int r0 = bm + mwarp + mi * 16 + gid;
#pragma unroll
        for (int half = 0; half < 2; half++) {
            int m = r0 + half * 8;
            size_t orow = ((size_t)(m & (BB - 1)) * TT + (m >> 11)) * II;
#pragma unroll
            for (int n = 0; n < 4; n++) {
                int c = nwarp + n * 8 + 2 * tig;
                float2 v;
                v.x = acc[mi][n][half * 2 + 0] + bias[c];
                v.y = acc[mi][n][half * 2 + 1] + bias[c + 1];
                *(float2*)(out + orow + c) = v;
            }
        }
    }
}

// ---------------------------------------------------------------------------
extern "C" void kernel_launch(void* const* d_in, const int* in_sizes, int n_in,
                              void* d_out, int out_size)
{
    const float* x     = (const float*)d_in[0];
    const float* h1_in = (const float*)d_in[1];
    const float* c1_in = (const float*)d_in[2];
    const float* h2_in = (const float*)d_in[3];
    const float* c2_in = (const float*)d_in[4];
    const float* w_ih1 = (const float*)d_in[5];
    const float* w_hh1 = (const float*)d_in[6];
    const float* b_ih1 = (const float*)d_in[7];
    const float* b_hh1 = (const float*)d_in[8];
    const float* w_ih2 = (const float*)d_in[9];
    const float* w_hh2 = (const float*)d_in[10];
    const float* b_ih2 = (const float*)d_in[11];
    const float* b_hh2 = (const float*)d_in[12];
    const float* fc_w  = (const float*)d_in[13];
    const float* fc_b  = (const float*)d_in[14];
    float* out = (float*)d_out;

    __half *h1p, *histp, *xhp, *wp1, *wp2, *fcwp;
    float *c1p, *c2p;
    cudaGetSymbolAddress((void**)&h1p, g_h1);
    cudaGetSymbolAddress((void**)&c1p, g_c1);
    cudaGetSymbolAddress((void**)&c2p, g_c2);
    cudaGetSymbolAddress((void**)&histp, g_hist);
    cudaGetSymbolAddress((void**)&xhp, g_xh);
    cudaGetSymbolAddress((void**)&wp1, g_wp1);
    cudaGetSymbolAddress((void**)&wp2, g_wp2);
    cudaGetSymbolAddress((void**)&fcwp, g_fcw);

    const size_t SN = (size_t)BB * HH;
    const size_t SB = SN * sizeof(float);

    // Prep
    round_h_kernel<<<1024, 256>>>(x, xhp, (size_t)BB * TT * II);
    round_h_kernel<<<256, 256>>>(h1_in, h1p, SN);
    round_h_kernel<<<256, 256>>>(h2_in, histp, SN);
    round_h_kernel<<<128, 256>>>(fc_w, fcwp, (size_t)II * HH);
    cudaMemcpyAsync(c1p, c1_in, SB, cudaMemcpyDeviceToDevice);
    cudaMemcpyAsync(c2p, c2_in, SB, cudaMemcpyDeviceToDevice);
    pack_w_kernel<<<2048, 256>>>(w_ih1, II, II, w_hh1, wp1, 36);
    pack_w_kernel<<<2048, 256>>>(w_ih2, HH, HH, w_hh2, wp2, 64);

    cudaFuncSetAttribute(step_gemm, cudaFuncAttributeMaxDynamicSharedMemorySize, SM_TOTAL);
    cudaFuncSetAttribute(fc_gemm, cudaFuncAttributeMaxDynamicSharedMemorySize, SM_TOTAL_FC);

    auto mkL1 = [&](int t) {
        GP p;
        p.A1 = xhp + (size_t)t * II; p.lda1 = TT * II; p.s1 = 4;
        p.A2 = h1p + (size_t)(t & 1) * SN;
        p.S = 36; p.Wp = wp1; p.b1 = b_ih1; p.b2 = b_hh1;
        p.H = h1p + (size_t)((t + 1) & 1) * SN; p.C = c1p;
        return p;
    };
    auto mkL2 = [&](int t) {
        GP p;
        p.A1 = h1p + (size_t)((t + 1) & 1) * SN; p.lda1 = HH; p.s1 = 32;
        p.A2 = histp + (size_t)t * SN;
        p.S = 64; p.Wp = wp2; p.b1 = b_ih2; p.b2 = b_hh2;
        p.H = histp + (size_t)(t + 1) * SN; p.C = c2p;
        return p;
    };

    {
        GP p = mkL1(0);
        step_gemm<<<256, 512, SM_TOTAL>>>(p, p, 256);
    }
    for (int t = 0; t < TT - 1; t++) {
        GP p2 = mkL2(t), p1 = mkL1(t + 1);
        step_gemm<<<512, 512, SM_TOTAL>>>(p2, p1, 256);
    }
    {
        GP p = mkL2(TT - 1);
        step_gemm<<<256, 512, SM_TOTAL>>>(p, p, 256);
    }

    // Batched fc over all timesteps
    fc_gemm<<<1024, 256, SM_TOTAL_FC>>>(histp + SN, fcwp, fc_b, out);

    // Final states: output_seq ‖ h1 ‖ c1 ‖ h2 ‖ c2
    float* tail = out + (size_t)BB * TT * II;
    h2f_kernel<<<256, 256>>>(h1p, tail + 0 * SN, SN);                       // H1[64] in buf 0
    cudaMemcpyAsync(tail + 1 * SN, c1p, SB, cudaMemcpyDeviceToDevice);
    h2f_kernel<<<256, 256>>>(histp + (size_t)TT * SN, tail + 2 * SN, SN);
    cudaMemcpyAsync(tail + 3 * SN, c2p, SB, cudaMemcpyDeviceToDevice);
}

// round 7
// speedup vs baseline: 7.6668x; 1.2867x over previous
#include <cuda_runtime.h>
#include <cuda_fp16.h>
#include <cstdint>
#include <cstddef>

#define BB 2048
#define TT 64
#define II 128
#define HH 1024

// Static device scratch (no allocations allowed). h states fp16; c states fp32.
__device__ __half g_h1[2][(size_t)BB * HH];
__device__ float  g_c1[(size_t)BB * HH];
__device__ float  g_c2[(size_t)BB * HH];
__device__ __half g_hist[(size_t)(TT + 1) * BB * HH];  // h2 history, slot 0 = initial
__device__ __half g_xh[(size_t)BB * TT * II];          // fp16-rounded x
__device__ __align__(256) __half g_wp1[(size_t)16 * 18 * 256 * 72];  // packed layer1 W
__device__ __align__(256) __half g_wp2[(size_t)16 * 32 * 256 * 72];  // packed layer2 W
__device__ __align__(256) __half g_fcw[(size_t)II * HH];             // fp16 fc W

// Fast activations: EX2/RCP MUFU based, ~2ulp, correct saturation at +-inf.
__device__ __forceinline__ float sigf(float x) {
    return __fdividef(1.f, 1.f + __expf(-x));
}
__device__ __forceinline__ float tanhf_fast(float x) {
    return 1.f - __fdividef(2.f, __expf(2.f * x) + 1.f);
}

__device__ __forceinline__ void mma16(float* c, const uint32_t* a, uint32_t b0, uint32_t b1) {
    asm volatile(
        "mma.sync.aligned.m16n8k16.row.col.f32.f16.f16.f32 "
        "{%0,%1,%2,%3},{%4,%5,%6,%7},{%8,%9},{%0,%1,%2,%3};"
        : "+f"(c[0]), "+f"(c[1]), "+f"(c[2]), "+f"(c[3])
        : "r"(a[0]), "r"(a[1]), "r"(a[2]), "r"(a[3]), "r"(b0), "r"(b1));
}

#define LDSM4(r, addr) \
    asm volatile("ldmatrix.sync.aligned.m8n8.x4.shared.b16 {%0,%1,%2,%3}, [%4];" \
                 : "=r"((r)[0]), "=r"((r)[1]), "=r"((r)[2]), "=r"((r)[3]) : "r"(addr))

__device__ __forceinline__ uint32_t s2u(const void* p) {
    uint32_t a;
    asm("{ .reg .u64 t; cvta.to.shared.u64 t, %1; cvt.u32.u64 %0, t; }" : "=r"(a) : "l"(p));
    return a;
}
__device__ __forceinline__ void cpa16(uint32_t d, const void* s) {
    asm volatile("cp.async.cg.shared.global [%0], [%1], 16;" :: "r"(d), "l"(s));
}
#define CP_COMMIT() asm volatile("cp.async.commit_group;" ::: "memory")
#define CP_WAIT2()  asm volatile("cp.async.wait_group 2;" ::: "memory")

// ---------------------------------------------------------------------------
// Prep kernels
// ---------------------------------------------------------------------------
__global__ void round_h_kernel(const float* __restrict__ in, __half* __restrict__ out, size_t n) {
    size_t stride = (size_t)gridDim.x * blockDim.x;
    for (size_t i = (size_t)blockIdx.x * blockDim.x + threadIdx.x; i < n; i += stride)
        out[i] = __float2half_rn(in[i]);
}
__global__ void h2f_kernel(const __half* __restrict__ in, float* __restrict__ out, size_t n) {
    size_t stride = (size_t)gridDim.x * blockDim.x;
    for (size_t i = (size_t)blockIdx.x * blockDim.x + threadIdx.x; i < n; i += stride)
        out[i] = __half2float(in[i]);
}

// Pack W into [tile_n][s64][l=256][72] fp16 smem-image (row stride 144B),
// gate-permuted. K stage = 64; j<64 real data, rest zero pad.
__global__ void pack_w_kernel(const float* __restrict__ Wih, int ldwi, int Ki,
                              const float* __restrict__ Whh,
                              __half* __restrict__ out, int S) {
    size_t total = (size_t)16 * S * 256 * 72;
    size_t stride = (size_t)gridDim.x * blockDim.x;
    for (size_t idx = (size_t)blockIdx.x * blockDim.x + threadIdx.x; idx < total; idx += stride) {
        int j = (int)(idx % 72); size_t r = idx / 72;
        int l = (int)(r % 256); r /= 256;
        int s = (int)(r % S);   int tn = (int)(r / S);
        float v = 0.f;
        if (j < 64) {
            int k = s * 64 + j;
            int wr = (l >> 6) * HH + tn * 64 + (l & 63);
            v = (k < Ki) ? Wih[(size_t)wr * ldwi + k]
                         : Whh[(size_t)wr * HH + (k - Ki)];
        }
        out[idx] = __float2half_rn(v);
    }
}

// ---------------------------------------------------------------------------
// Gate GEMM + fused LSTM cell. Tile 128x256 (gate-permuted N), 512 threads.
// 16 warps 4(m)x4(n), each 32x64. fp16 m16n8k16, ldmatrix feed.
// K staged 64 wide, 3-deep cp.async pipeline. Rows 144B (bank-clean).
// ---------------------------------------------------------------------------
struct GP {
    const __half* A1; long lda1; int s1;   // s1 = #K64 stages from A1
    const __half* A2;                      // lda = HH
    int S;                                 // total K64 stages
    const __half* Wp;                      // packed weights base
    const float* b1; const float* b2;
    __half* H; float* C;
};

#define A_BYTES 18432              // 128 * 144
#define SM_BUF  55296              // A 128*144 + B 256*144
#define SM_TOTAL (1024 + 3 * SM_BUF)

__device__ __forceinline__ void gate_body(const GP& p, int bid, char* smem) {
    const uint32_t sb = s2u(smem);
    float* bias = (float*)smem;
    const int tid = threadIdx.x, lane = tid & 31, wid = tid >> 5;
    const int tile_m = bid >> 4, tile_n = bid & 15;
    const int bm = tile_m * 128;
    const int wm = wid & 3, wn = wid >> 2;        // 4x4 warp grid
    const int mwarp = wm * 32, nwarp = wn * 64;

    if (tid < 256) {   // summed permuted bias
        int wr = (tid >> 6) * HH + tile_n * 64 + (tid & 63);
        bias[tid] = p.b1[wr] + p.b2[wr];
    }

    float acc[2][8][4];
#pragma unroll
    for (int a = 0; a < 2; a++)
#pragma unroll
        for (int b = 0; b < 8; b++)
#pragma unroll
            for (int c = 0; c < 4; c++) acc[a][b][c] = 0.f;

    const __half* wp_base = p.Wp + (size_t)tile_n * p.S * (256 * 72);

    // ldmatrix per-thread offsets (bytes), 144B row stride
    const uint32_t arow = (uint32_t)((mwarp + (lane & 7) + ((lane >> 3) & 1) * 8) * 144
                                     + (lane >> 4) * 16);
    const uint32_t brow = (uint32_t)((nwarp + (lane & 7) + (lane >> 4) * 8) * 144
                                     + ((lane >> 3) & 1) * 16);

    auto load = [&](int s) {
        const int buf = s % 3;
        const __half* A; long lda; int kk;
        if (s < p.s1) { A = p.A1; lda = p.lda1; kk = s * 64; }
        else          { A = p.A2; lda = HH;     kk = (s - p.s1) * 64; }
        const uint32_t ab = sb + 1024 + buf * SM_BUF;
        const __half* Arow = A + (size_t)bm * lda + kk;
#pragma unroll
        for (int i = 0; i < 2; i++) {   // A: 128 rows x 8 granules = 1024
            int c = tid + i * 512, row = c >> 3, kc = c & 7;
            cpa16(ab + row * 144 + kc * 16, Arow + (size_t)row * lda + kc * 8);
        }
        const uint32_t bb2 = ab + A_BYTES;
        const __half* Ws = wp_base + (size_t)s * (256 * 72);
#pragma unroll
        for (int i = 0; i < 4; i++) {   // B: 256 rows x 8 granules = 2048
            int c = tid + i * 512, row = c >> 3, kc = c & 7;
            cpa16(bb2 + row * 144 + kc * 16, Ws + row * 72 + kc * 8);
        }
    };

    load(0); CP_COMMIT();
    load(1); CP_COMMIT();
    load(2); CP_COMMIT();

    for (int s = 0; s < p.S; s++) {
        CP_WAIT2();
        __syncthreads();
        {
            const uint32_t abase = sb + 1024 + (s % 3) * SM_BUF;
            const uint32_t bbase = abase + A_BYTES;
#pragma unroll
            for (int kc = 0; kc < 4; kc++) {   // four k16 chunks per K64 stage
                uint32_t af[2][4], bf[4][4];
#pragma unroll
                for (int mi = 0; mi < 2; mi++)
                    LDSM4(af[mi], abase + arow + mi * 2304 + kc * 32);
#pragma unroll
                for (int nb = 0; nb < 4; nb++)
                    LDSM4(bf[nb], bbase + brow + nb * 2304 + kc * 32);
#pragma unroll
                for (int mi = 0; mi < 2; mi++)
#pragma unroll
                    for (int nb = 0; nb < 4; nb++) {
                        mma16(acc[mi][2 * nb],     af[mi], bf[nb][0], bf[nb][1]);
                        mma16(acc[mi][2 * nb + 1], af[mi], bf[nb][2], bf[nb][3]);
                    }
            }
        }
        __syncthreads();
        if (s + 3 < p.S) load(s + 3);
        CP_COMMIT();
    }

    // Epilogue: two 64-row phases staged through smem (64 x 260 floats)
    float* stage = (float*)(smem + 1024);
    const int gid = lane >> 2, tig = lane & 3;
#pragma unroll
    for (int ph = 0; ph < 2; ph++) {
        if ((wm >> 1) == ph) {
#pragma unroll
            for (int mi = 0; mi < 2; mi++)
#pragma unroll
                for (int n = 0; n < 8; n++) {
                    int r0 = (wm & 1) * 32 + mi * 16 + gid;
                    int c = nwarp + n * 8 + 2 * tig;
                    stage[r0 * 260 + c]           = acc[mi][n][0];
                    stage[r0 * 260 + c + 1]       = acc[mi][n][1];
                    stage[(r0 + 8) * 260 + c]     = acc[mi][n][2];
                    stage[(r0 + 8) * 260 + c + 1] = acc[mi][n][3];
                }
        }
        __syncthreads();
        {
            int r = tid >> 3, u0 = (tid & 7) * 8;
            int m = bm + ph * 64 + r;
            float* crow = p.C + (size_t)m * HH + tile_n * 64;
            __half* hrow = p.H + (size_t)m * HH + tile_n * 64;
#pragma unroll
            for (int jb = 0; jb < 2; jb++) {
                float4 cv = *(float4*)(crow + u0 + jb * 4);
                float* cvp = (float*)&cv;
                __half hv[4];
#pragma unroll
                for (int e = 0; e < 4; e++) {
                    int u = u0 + jb * 4 + e;
                    float iv = sigf(stage[r * 260 + u] + bias[u]);
                    float fv = sigf(stage[r * 260 + 64 + u] + bias[64 + u]);
                    float gv = tanhf_fast(stage[r * 260 + 128 + u] + bias[128 + u]);
                    float ov = sigf(stage[r * 260 + 192 + u] + bias[192 + u]);
                    float cn = fv * cvp[e] + iv * gv;
                    cvp[e] = cn;
                    hv[e] = __float2half_rn(ov * tanhf_fast(cn));
                }
                *(float4*)(crow + u0 + jb * 4) = cv;
                *(uint2*)(hrow + u0 + jb * 4) = *(uint2*)hv;
            }
        }
        __syncthreads();
    }
}

__global__ __launch_bounds__(512, 1)
void step_gemm(GP pa, GP pb, int nb_a) {
    extern __shared__ __align__(16) char smem[];
    if ((int)blockIdx.x < nb_a) gate_body(pa, blockIdx.x, smem);
    else                        gate_body(pb, blockIdx.x - nb_a, smem);
}

// ---------------------------------------------------------------------------
// Batched fc over the whole h2 history (fp16, 256 threads, tile 128x128).
// ---------------------------------------------------------------------------
#define SM_BUF_FC 20480            // A 128*80 + B 128*80
#define SM_TOTAL_FC (1024 + 3 * SM_BUF_FC)

__global__ __launch_bounds__(256, 1)
void fc_gemm(const __half* __restrict__ A, const __half* __restrict__ W,
             const float* __restrict__ bias_g, float* __restrict__ out)
{
    extern __shared__ __align__(16) char smem[];
    const uint32_t sb = s2u(smem);
    float* bias = (float*)smem;
    const int tid = threadIdx.x, lane = tid & 31, wid = tid >> 5;
    const int gid = lane >> 2, tig = lane & 3;
    const int bm = blockIdx.x * 128;
    const int mwarp = (wid >> 2) * 64, nwarp = (wid & 3) * 32;

    if (tid < II) bias[tid] = bias_g[tid];

    float acc[4][4][4];
#pragma unroll
    for (int a = 0; a < 4; a++)
#pragma unroll
        for (int b = 0; b < 4; b++)
#pragma unroll
            for (int c = 0; c < 4; c++) acc[a][b][c] = 0.f;

    const uint32_t arow = (uint32_t)((mwarp + (lane & 7) + ((lane >> 3) & 1) * 8) * 80
                                     + (lane >> 4) * 16);
    const uint32_t brow = (uint32_t)((nwarp + (lane & 7) + (lane >> 4) * 8) * 80
                                     + ((lane >> 3) & 1) * 16);

    auto load = [&](int s) {
        const int buf = s % 3;
        const uint32_t ab = sb + 1024 + buf * SM_BUF_FC;
        const uint32_t bb2 = ab + 10240;
        int kk = s * 32;
#pragma unroll
        for (int i = 0; i < 2; i++) {
            int c = tid + i * 256, row = c >> 2, kc = c & 3;
            cpa16(ab + row * 80 + kc * 16, A + (size_t)(bm + row) * HH + kk + kc * 8);
        }
#pragma unroll
        for (int i = 0; i < 2; i++) {
            int c = tid + i * 256, row = c >> 2, kc = c & 3;
            cpa16(bb2 + row * 80 + kc * 16, W + (size_t)row * HH + kk + kc * 8);
        }
    };

    load(0); CP_COMMIT();
    load(1); CP_COMMIT();
    load(2); CP_COMMIT();

    for (int s = 0; s < 32; s++) {
        CP_WAIT2();
        __syncthreads();
        {
            const uint32_t abase = sb + 1024 + (s % 3) * SM_BUF_FC;
            const uint32_t bbase = abase + 10240;
#pragma unroll
            for (int kc = 0; kc < 2; kc++) {
                uint32_t af[4][4], bf[2][4];
#pragma unroll
                for (int mi = 0; mi < 4; mi++)
                    LDSM4(af[mi], abase + arow + mi * 1280 + kc * 32);
#pragma unroll
                for (int nb = 0; nb < 2; nb++)
                    LDSM4(bf[nb], bbase + brow + nb * 1280 + kc * 32);
#pragma unroll
                for (int mi = 0; mi < 4; mi++)
#pragma unroll
                    for (int nb = 0; nb < 2; nb++) {
                        mma16(acc[mi][2 * nb],     af[mi], bf[nb][0], bf[nb][1]);
                        mma16(acc[mi][2 * nb + 1], af[mi], bf[nb][2], bf[nb][3]);
                    }
            }
        }
        __syncthreads();
        if (s + 3 < 32) load(s + 3);
        CP_COMMIT();
    }

#pragma unroll
    for (int mi = 0; mi < 4; mi++) {
        int r0 = bm + mwarp + mi * 16 + gid;
#pragma unroll
        for (int half = 0; half < 2; half++) {
            int m = r0 + half * 8;
            size_t orow = ((size_t)(m & (BB - 1)) * TT + (m >> 11)) * II;
#pragma unroll
            for (int n = 0; n < 4; n++) {
                int c = nwarp + n * 8 + 2 * tig;
                float2 v;
                v.x = acc[mi][n][half * 2 + 0] + bias[c];
                v.y = acc[mi][n][half * 2 + 1] + bias[c + 1];
                *(float2*)(out + orow + c) = v;
            }
        }
    }
}

// ---------------------------------------------------------------------------
extern "C" void kernel_launch(void* const* d_in, const int* in_sizes, int n_in,
                              void* d_out, int out_size)
{
    const float* x     = (const float*)d_in[0];
    const float* h1_in = (const float*)d_in[1];
    const float* c1_in = (const float*)d_in[2];
    const float* h2_in = (const float*)d_in[3];
    const float* c2_in = (const float*)d_in[4];
    const float* w_ih1 = (const float*)d_in[5];
    const float* w_hh1 = (const float*)d_in[6];
    const float* b_ih1 = (const float*)d_in[7];
    const float* b_hh1 = (const float*)d_in[8];
    const float* w_ih2 = (const float*)d_in[9];
    const float* w_hh2 = (const float*)d_in[10];
    const float* b_ih2 = (const float*)d_in[11];
    const float* b_hh2 = (const float*)d_in[12];
    const float* fc_w  = (const float*)d_in[13];
    const float* fc_b  = (const float*)d_in[14];
    float* out = (float*)d_out;

    __half *h1p, *histp, *xhp, *wp1, *wp2, *fcwp;
    float *c1p, *c2p;
    cudaGetSymbolAddress((void**)&h1p, g_h1);
    cudaGetSymbolAddress((void**)&c1p, g_c1);
    cudaGetSymbolAddress((void**)&c2p, g_c2);
    cudaGetSymbolAddress((void**)&histp, g_hist);
    cudaGetSymbolAddress((void**)&xhp, g_xh);
    cudaGetSymbolAddress((void**)&wp1, g_wp1);
    cudaGetSymbolAddress((void**)&wp2, g_wp2);
    cudaGetSymbolAddress((void**)&fcwp, g_fcw);

    const size_t SN = (size_t)BB * HH;
    const size_t SB = SN * sizeof(float);

    // Prep
    round_h_kernel<<<1024, 256>>>(x, xhp, (size_t)BB * TT * II);
    round_h_kernel<<<256, 256>>>(h1_in, h1p, SN);
    round_h_kernel<<<256, 256>>>(h2_in, histp, SN);
    round_h_kernel<<<128, 256>>>(fc_w, fcwp, (size_t)II * HH);
    cudaMemcpyAsync(c1p, c1_in, SB, cudaMemcpyDeviceToDevice);
    cudaMemcpyAsync(c2p, c2_in, SB, cudaMemcpyDeviceToDevice);
    pack_w_kernel<<<2048, 256>>>(w_ih1, II, II, w_hh1, wp1, 18);
    pack_w_kernel<<<2048, 256>>>(w_ih2, HH, HH, w_hh2, wp2, 32);

    cudaFuncSetAttribute(step_gemm, cudaFuncAttributeMaxDynamicSharedMemorySize, SM_TOTAL);
    cudaFuncSetAttribute(fc_gemm, cudaFuncAttributeMaxDynamicSharedMemorySize, SM_TOTAL_FC);

    auto mkL1 = [&](int t) {   // K = 128(x) + 1024(h) = 18 K64 stages
        GP p;
        p.A1 = xhp + (size_t)t * II; p.lda1 = TT * II; p.s1 = 2;
        p.A2 = h1p + (size_t)(t & 1) * SN;
        p.S = 18; p.Wp = wp1; p.b1 = b_ih1; p.b2 = b_hh1;
        p.H = h1p + (size_t)((t + 1) & 1) * SN; p.C = c1p;
        return p;
    };
    auto mkL2 = [&](int t) {   // K = 1024 + 1024 = 32 K64 stages
        GP p;
        p.A1 = h1p + (size_t)((t + 1) & 1) * SN; p.lda1 = HH; p.s1 = 16;
        p.A2 = histp + (size_t)t * SN;
        p.S = 32; p.Wp = wp2; p.b1 = b_ih2; p.b2 = b_hh2;
        p.H = histp + (size_t)(t + 1) * SN; p.C = c2p;
        return p;
    };

    {
        GP p = mkL1(0);
        step_gemm<<<256, 512, SM_TOTAL>>>(p, p, 256);
    }
    for (int t = 0; t < TT - 1; t++) {
        GP p2 = mkL2(t), p1 = mkL1(t + 1);
        step_gemm<<<512, 512, SM_TOTAL>>>(p2, p1, 256);
    }
    {
        GP p = mkL2(TT - 1);
        step_gemm<<<256, 512, SM_TOTAL>>>(p, p, 256);
    }

    // Batched fc over all timesteps
    fc_gemm<<<1024, 256, SM_TOTAL_FC>>>(histp + SN, fcwp, fc_b, out);

    // Final states: output_seq ‖ h1 ‖ c1 ‖ h2 ‖ c2
    float* tail = out + (size_t)BB * TT * II;
    h2f_kernel<<<256, 256>>>(h1p, tail + 0 * SN, SN);   // H1[64] in buf 0
    cudaMemcpyAsync(tail + 1 * SN, c1p, SB, cudaMemcpyDeviceToDevice);
    h2f_kernel<<<256, 256>>>(histp + (size_t)TT * SN, tail + 2 * SN, SN);
    cudaMemcpyAsync(tail + 3 * SN, c2p, SB, cudaMemcpyDeviceToDevice);
}